// round 3
// baseline (speedup 1.0000x reference)
#include <cuda_runtime.h>

// ---------------------------------------------------------------------------
// Attention_18476949308128 — round 2: 128x128x8 SIMT GEMM + fused attention
// B=2, S=2048, D_EMBED=D_MODEL=1024, H=16, d_k=64
// Pipeline:
//   1) Q/K/V projections       gemm_nt128 (NT + bias)
//   2) scores_exp              E = exp(QK^T + maskadd), rowsum  (fused)
//   3) rescale_attnv           attn = E/rowsum (in place) ; O = attn @ V
//   4) out projection          gemm_nt128
// ---------------------------------------------------------------------------

// Scratch (static __device__ globals: allocation-free per harness rules)
__device__ float g_Q[4096 * 1024];
__device__ float g_K[4096 * 1024];
__device__ float g_V[4096 * 1024];
__device__ float g_C[4096 * 1024];      // blended, [b, q, h, d] == [4096,1024]
__device__ float g_rowsum[65536];
__device__ float g_attn[134217728];      // fallback if attn not in d_out

// ============================================================================
// 128x128 tile, BK=8, double-buffered, 8x8 microtile. C = A @ B^T + bias
// A: [M,K] row-major (lda), B: [N,K] row-major (ldb), C: [M,N] (ldc)
// ============================================================================
__global__ __launch_bounds__(256, 2) void gemm_nt128(
    const float* __restrict__ A, const float* __restrict__ B,
    float* __restrict__ C, const float* __restrict__ bias,
    int K, int lda, int ldb, int ldc)
{
    __shared__ float As[2][8][128];
    __shared__ float Bs[2][8][128];

    int t  = threadIdx.x;
    int m0 = blockIdx.y * 128;
    int n0 = blockIdx.x * 128;
    int lr = t >> 1;             // 0..127
    int lc = (t & 1) * 4;        // 0 or 4
    int tx = t & 15, ty = t >> 4;

    const float* Aptr = A + (long)(m0 + lr) * lda + lc;
    const float* Bptr = B + (long)(n0 + lr) * ldb + lc;

    float4 a4 = *(const float4*)Aptr;
    float4 b4 = *(const float4*)Bptr;
    As[0][lc + 0][lr] = a4.x; As[0][lc + 1][lr] = a4.y;
    As[0][lc + 2][lr] = a4.z; As[0][lc + 3][lr] = a4.w;
    Bs[0][lc + 0][lr] = b4.x; Bs[0][lc + 1][lr] = b4.y;
    Bs[0][lc + 2][lr] = b4.z; Bs[0][lc + 3][lr] = b4.w;
    __syncthreads();

    float acc[8][8] = {};
    int buf = 0;

    for (int k0 = 8; k0 < K; k0 += 8) {
        a4 = *(const float4*)(Aptr + k0);
        b4 = *(const float4*)(Bptr + k0);
#pragma unroll
        for (int k = 0; k < 8; k++) {
            float4 A0 = *(const float4*)&As[buf][k][ty * 4];
            float4 A1 = *(const float4*)&As[buf][k][ty * 4 + 64];
            float4 B0 = *(const float4*)&Bs[buf][k][tx * 4];
            float4 B1 = *(const float4*)&Bs[buf][k][tx * 4 + 64];
            float av[8] = {A0.x, A0.y, A0.z, A0.w, A1.x, A1.y, A1.z, A1.w};
            float bv[8] = {B0.x, B0.y, B0.z, B0.w, B1.x, B1.y, B1.z, B1.w};
#pragma unroll
            for (int i = 0; i < 8; i++)
#pragma unroll
                for (int j = 0; j < 8; j++)
                    acc[i][j] += av[i] * bv[j];
        }
        int nb = buf ^ 1;
        As[nb][lc + 0][lr] = a4.x; As[nb][lc + 1][lr] = a4.y;
        As[nb][lc + 2][lr] = a4.z; As[nb][lc + 3][lr] = a4.w;
        Bs[nb][lc + 0][lr] = b4.x; Bs[nb][lc + 1][lr] = b4.y;
        Bs[nb][lc + 2][lr] = b4.z; Bs[nb][lc + 3][lr] = b4.w;
        __syncthreads();
        buf = nb;
    }
#pragma unroll
    for (int k = 0; k < 8; k++) {
        float4 A0 = *(const float4*)&As[buf][k][ty * 4];
        float4 A1 = *(const float4*)&As[buf][k][ty * 4 + 64];
        float4 B0 = *(const float4*)&Bs[buf][k][tx * 4];
        float4 B1 = *(const float4*)&Bs[buf][k][tx * 4 + 64];
        float av[8] = {A0.x, A0.y, A0.z, A0.w, A1.x, A1.y, A1.z, A1.w};
        float bv[8] = {B0.x, B0.y, B0.z, B0.w, B1.x, B1.y, B1.z, B1.w};
#pragma unroll
        for (int i = 0; i < 8; i++)
#pragma unroll
            for (int j = 0; j < 8; j++)
                acc[i][j] += av[i] * bv[j];
    }

#pragma unroll
    for (int jj = 0; jj < 2; jj++) {
        float4 bvec = *(const float4*)(bias + n0 + tx * 4 + jj * 64);
#pragma unroll
        for (int i = 0; i < 8; i++) {
            int row = m0 + ((i < 4) ? ty * 4 + i : 64 + ty * 4 + (i - 4));
            float4 v;
            v.x = acc[i][jj * 4 + 0] + bvec.x;
            v.y = acc[i][jj * 4 + 1] + bvec.y;
            v.z = acc[i][jj * 4 + 2] + bvec.z;
            v.w = acc[i][jj * 4 + 3] + bvec.w;
            *(float4*)(C + (long)row * ldc + n0 + tx * 4 + jj * 64) = v;
        }
    }
}

// ============================================================================
// scores_exp: per (qtile, bh): E[q, k] = exp(Q·K^T + (1-mask)*NEG), rowsum
// block = 128 q-rows, sweeps all 2048 k in 16 tiles of 128. 256 threads.
// ============================================================================
__global__ __launch_bounds__(256) void scores_exp(
    const float* __restrict__ Q, const float* __restrict__ Kp,
    const float* __restrict__ mask,
    float* __restrict__ E, float* __restrict__ rowsum)
{
    extern __shared__ float smem[];
    float* Qs   = smem;                    // [64][128]
    float* Ks   = smem + 64 * 128;         // [64][132]
    float* part = Ks + 64 * 132;           // [16][128]

    int t  = threadIdx.x;
    int qt = blockIdx.x, bh = blockIdx.y;
    int b = bh >> 4, h = bh & 15;
    const float* Qh   = Q  + (long)b * 2048 * 1024 + h * 64;
    const float* Kh   = Kp + (long)b * 2048 * 1024 + h * 64;
    float*       Ebh  = E  + ((long)bh * 2048 + qt * 128) * 2048;
    const float* mrow = mask + (long)b * 2048;

    // load Q tile [128 q][64 d] transposed -> Qs[d][q]
    {
        int row = t >> 1;
        int d0  = (t & 1) * 32;
        const float* src = Qh + (long)(qt * 128 + row) * 1024 + d0;
#pragma unroll
        for (int j = 0; j < 8; j++) {
            float4 v = *(const float4*)(src + j * 4);
            Qs[(d0 + j * 4 + 0) * 128 + row] = v.x;
            Qs[(d0 + j * 4 + 1) * 128 + row] = v.y;
            Qs[(d0 + j * 4 + 2) * 128 + row] = v.z;
            Qs[(d0 + j * 4 + 3) * 128 + row] = v.w;
        }
    }
    __syncthreads();

    int tx = t & 15, ty = t >> 4;
    float rs[8] = {};

    for (int kt = 0; kt < 16; kt++) {
        // load K tile [128 k][64 d] transposed -> Ks[d][k]
        {
            int row = t >> 1;
            int d0  = (t & 1) * 32;
            const float* src = Kh + (long)(kt * 128 + row) * 1024 + d0;
#pragma unroll
            for (int j = 0; j < 8; j++) {
                float4 v = *(const float4*)(src + j * 4);
                Ks[(d0 + j * 4 + 0) * 132 + row] = v.x;
                Ks[(d0 + j * 4 + 1) * 132 + row] = v.y;
                Ks[(d0 + j * 4 + 2) * 132 + row] = v.z;
                Ks[(d0 + j * 4 + 3) * 132 + row] = v.w;
            }
        }
        __syncthreads();

        float acc[8][8] = {};
#pragma unroll
        for (int d = 0; d < 64; d++) {
            float4 A0 = *(const float4*)&Qs[d * 128 + ty * 4];
            float4 A1 = *(const float4*)&Qs[d * 128 + ty * 4 + 64];
            float4 B0 = *(const float4*)&Ks[d * 132 + tx * 4];
            float4 B1 = *(const float4*)&Ks[d * 132 + tx * 4 + 64];
            float av[8] = {A0.x, A0.y, A0.z, A0.w, A1.x, A1.y, A1.z, A1.w};
            float bv[8] = {B0.x, B0.y, B0.z, B0.w, B1.x, B1.y, B1.z, B1.w};
#pragma unroll
            for (int i = 0; i < 8; i++)
#pragma unroll
                for (int j = 0; j < 8; j++)
                    acc[i][j] += av[i] * bv[j];
        }

        // exp + mask + store E + rowsum partials
#pragma unroll
        for (int jj = 0; jj < 2; jj++) {
            int cbase = kt * 128 + tx * 4 + jj * 64;
            float m0v = (1.0f - mrow[cbase + 0]) * (-1e9f);
            float m1v = (1.0f - mrow[cbase + 1]) * (-1e9f);
            float m2v = (1.0f - mrow[cbase + 2]) * (-1e9f);
            float m3v = (1.0f - mrow[cbase + 3]) * (-1e9f);
#pragma unroll
            for (int i = 0; i < 8; i++) {
                int row = (i < 4) ? ty * 4 + i : 64 + ty * 4 + (i - 4);
                float4 ev;
                ev.x = __expf(acc[i][jj * 4 + 0] + m0v);
                ev.y = __expf(acc[i][jj * 4 + 1] + m1v);
                ev.z = __expf(acc[i][jj * 4 + 2] + m2v);
                ev.w = __expf(acc[i][jj * 4 + 3] + m3v);
                rs[i] += (ev.x + ev.y) + (ev.z + ev.w);
                *(float4*)(Ebh + (long)row * 2048 + cbase) = ev;
            }
        }
        __syncthreads();   // before Ks overwrite
    }

    // deterministic rowsum reduction
#pragma unroll
    for (int i = 0; i < 8; i++) {
        int row = (i < 4) ? ty * 4 + i : 64 + ty * 4 + (i - 4);
        part[tx * 128 + row] = rs[i];
    }
    __syncthreads();
    if (t < 128) {
        float s = 0.f;
#pragma unroll
        for (int x = 0; x < 16; x++) s += part[x * 128 + t];
        rowsum[(long)bh * 2048 + qt * 128 + t] = s;
    }
}

// ============================================================================
// rescale_attnv: attn = E / rowsum (in place), O[128,64] += attn @ V
// block = (qtile, bh), 256 threads, thread tile 8q x 4d
// ============================================================================
__global__ __launch_bounds__(256) void rescale_attnv(
    float* __restrict__ E, const float* __restrict__ V,
    const float* __restrict__ rowsum, float* __restrict__ Cc)
{
    extern __shared__ float smem[];
    float* Es   = smem;                  // [128][132]
    float* Vs   = Es + 128 * 132;        // [128][64]
    float* invs = Vs + 128 * 64;         // [128]

    int t  = threadIdx.x;
    int qt = blockIdx.x, bh = blockIdx.y;
    int b = bh >> 4, h = bh & 15;
    float*       Ebh = E + ((long)bh * 2048 + qt * 128) * 2048;
    const float* Vh  = V + (long)b * 2048 * 1024 + h * 64;
    float*       Ch  = Cc + ((long)b * 2048 + qt * 128) * 1024 + h * 64;

    if (t < 128) invs[t] = 1.0f / rowsum[(long)bh * 2048 + qt * 128 + t];
    __syncthreads();

    int tx = t & 15, ty = t >> 4;
    float acc[8][4] = {};

    for (int kt = 0; kt < 16; kt++) {
        // V tile [128 k][64 d] natural layout
        {
            int row = t >> 1, c0 = (t & 1) * 32;
            const float* src = Vh + (long)(kt * 128 + row) * 1024 + c0;
#pragma unroll
            for (int j = 0; j < 8; j++)
                *(float4*)&Vs[row * 64 + c0 + j * 4] = *(const float4*)(src + j * 4);
        }
        // E tile: read, scale, write back (final attn), stage in smem
        {
            int row = t >> 1, c0 = (t & 1) * 64;
            float inv = invs[row];
            float* gp = Ebh + (long)row * 2048 + kt * 128 + c0;
#pragma unroll
            for (int j = 0; j < 16; j++) {
                float4 v = *(const float4*)(gp + j * 4);
                v.x *= inv; v.y *= inv; v.z *= inv; v.w *= inv;
                *(float4*)(gp + j * 4) = v;
                *(float4*)&Es[row * 132 + c0 + j * 4] = v;
            }
        }
        __syncthreads();

#pragma unroll 2
        for (int k = 0; k < 128; k += 2) {
            float4 v0 = *(const float4*)&Vs[k * 64 + tx * 4];
            float4 v1 = *(const float4*)&Vs[(k + 1) * 64 + tx * 4];
#pragma unroll
            for (int i = 0; i < 8; i++) {
                float2 e = *(const float2*)&Es[(ty * 8 + i) * 132 + k];
                acc[i][0] += e.x * v0.x + e.y * v1.x;
                acc[i][1] += e.x * v0.y + e.y * v1.y;
                acc[i][2] += e.x * v0.z + e.y * v1.z;
                acc[i][3] += e.x * v0.w + e.y * v1.w;
            }
        }
        __syncthreads();
    }

#pragma unroll
    for (int i = 0; i < 8; i++) {
        float4 o;
        o.x = acc[i][0]; o.y = acc[i][1]; o.z = acc[i][2]; o.w = acc[i][3];
        *(float4*)(Ch + (long)(ty * 8 + i) * 1024 + tx * 4) = o;
    }
}

// ============================================================================
extern "C" void kernel_launch(void* const* d_in, const int* in_sizes, int n_in,
                              void* d_out, int out_size)
{
    (void)in_sizes; (void)n_in;
    const float* query        = (const float*)d_in[0];
    const float* input_embeds = (const float*)d_in[1];
    const float* mask         = (const float*)d_in[2];
    const float* wq_w = (const float*)d_in[3];
    const float* wq_b = (const float*)d_in[4];
    const float* wk_w = (const float*)d_in[5];
    const float* wk_b = (const float*)d_in[6];
    const float* wv_w = (const float*)d_in[7];
    const float* wv_b = (const float*)d_in[8];
    const float* wo_w = (const float*)d_in[9];
    const float* wo_b = (const float*)d_in[10];
    float* out = (float*)d_out;

    float *Q, *K, *V, *Cc, *rowsum, *attn_scratch;
    cudaGetSymbolAddress((void**)&Q,  g_Q);
    cudaGetSymbolAddress((void**)&K,  g_K);
    cudaGetSymbolAddress((void**)&V,  g_V);
    cudaGetSymbolAddress((void**)&Cc, g_C);
    cudaGetSymbolAddress((void**)&rowsum, g_rowsum);
    cudaGetSymbolAddress((void**)&attn_scratch, g_attn);

    const long OUT_E  = 4194304L;    // 2*2048*1024
    const long ATTN_E = 134217728L;  // 2*16*2048*2048
    float* attn = ((long)out_size >= OUT_E + ATTN_E) ? (out + OUT_E) : attn_scratch;

    const int SMEM_SCORES  = (64 * 128 + 64 * 132 + 16 * 128) * 4;   // 74752
    const int SMEM_RESCALE = (128 * 132 + 128 * 64 + 128) * 4;       // 100864
    cudaFuncSetAttribute(scores_exp, cudaFuncAttributeMaxDynamicSharedMemorySize, SMEM_SCORES);
    cudaFuncSetAttribute(rescale_attnv, cudaFuncAttributeMaxDynamicSharedMemorySize, SMEM_RESCALE);

    dim3 blk(256);

    // 1) Projections: [4096,1024] = X @ W^T + b
    dim3 gProj(1024 / 128, 4096 / 128);
    gemm_nt128<<<gProj, blk>>>(query,        wq_w, Q, wq_b, 1024, 1024, 1024, 1024);
    gemm_nt128<<<gProj, blk>>>(input_embeds, wk_w, K, wk_b, 1024, 1024, 1024, 1024);
    gemm_nt128<<<gProj, blk>>>(input_embeds, wv_w, V, wv_b, 1024, 1024, 1024, 1024);

    // 2) E = exp(scores + maskadd), rowsum
    dim3 gS(16, 32);
    scores_exp<<<gS, blk, SMEM_SCORES>>>(Q, K, mask, attn, rowsum);

    // 3) attn = E/rowsum (in place), O = attn @ V  -> Cc [b,q,h,d]
    rescale_attnv<<<gS, blk, SMEM_RESCALE>>>(attn, V, rowsum, Cc);

    // 4) out = concat @ wo^T + wo_b
    gemm_nt128<<<gProj, blk>>>(Cc, wo_w, out, wo_b, 1024, 1024, 1024, 1024);
}

// round 5
// speedup vs baseline: 1.3968x; 1.3968x over previous
#include <cuda_runtime.h>
#include <cuda_bf16.h>
#include <cstdint>

typedef __nv_bfloat16 bf16;

// ---------------------------------------------------------------------------
// HMMA helpers (plain sm_103-safe PTX: mma.sync / ldmatrix / cp.async)
// ---------------------------------------------------------------------------
static __device__ __forceinline__ uint32_t smem_u32(const void* p) {
    uint32_t a;
    asm("{ .reg .u64 t; cvta.to.shared.u64 t, %1; cvt.u32.u64 %0, t; }" : "=r"(a) : "l"(p));
    return a;
}
static __device__ __forceinline__ void mma16816(float* c, const uint32_t* a, const uint32_t* b) {
    asm volatile("mma.sync.aligned.m16n8k16.row.col.f32.bf16.bf16.f32 "
        "{%0,%1,%2,%3}, {%4,%5,%6,%7}, {%8,%9}, {%0,%1,%2,%3};"
        : "+f"(c[0]), "+f"(c[1]), "+f"(c[2]), "+f"(c[3])
        : "r"(a[0]), "r"(a[1]), "r"(a[2]), "r"(a[3]), "r"(b[0]), "r"(b[1]));
}
static __device__ __forceinline__ void mma3(float* c, const uint32_t* ah, const uint32_t* al,
                                            const uint32_t* bh, const uint32_t* bl) {
    mma16816(c, ah, bh); mma16816(c, ah, bl); mma16816(c, al, bh);
}
static __device__ __forceinline__ void ldsm4(uint32_t* r, uint32_t a) {
    asm volatile("ldmatrix.sync.aligned.m8n8.x4.shared.b16 {%0,%1,%2,%3}, [%4];"
        : "=r"(r[0]), "=r"(r[1]), "=r"(r[2]), "=r"(r[3]) : "r"(a));
}
// A-fragment 16x16 at (m0,k0); row stride sbytes
static __device__ __forceinline__ void ldsmA(uint32_t* r, uint32_t base, int m0, int k0, int sbytes, int lane) {
    ldsm4(r, base + (uint32_t)((m0 + (lane & 7) + ((lane >> 3) & 1) * 8) * sbytes
                               + (k0 + ((lane >> 4) << 3)) * 2));
}
// B-fragments: two n-tiles (16 rows of B[n,k]) x k16 at (n0,k0); r[0..1]=tile0, r[2..3]=tile1
static __device__ __forceinline__ void ldsmB(uint32_t* r, uint32_t base, int n0, int k0, int sbytes, int lane) {
    ldsm4(r, base + (uint32_t)((n0 + (lane & 7) + ((lane >> 4) << 3)) * sbytes
                               + (k0 + (((lane >> 3) & 1) << 3)) * 2));
}
#define CP16(sm_, gp_) asm volatile("cp.async.cg.shared.global [%0], [%1], 16;" :: "r"(sm_), "l"(gp_))
#define CPCOMMIT()     asm volatile("cp.async.commit_group;")
#define CPWAIT(n)      asm volatile("cp.async.wait_group %0;" :: "n"(n))

static __device__ __forceinline__ void split8(const float* f, uint4* hv, uint4* lv) {
    __align__(16) bf16 h[8], l[8];
#pragma unroll
    for (int j = 0; j < 8; j++) {
        h[j] = __float2bfloat16(f[j]);
        l[j] = __float2bfloat16(f[j] - __bfloat162float(h[j]));
    }
    *hv = *(uint4*)h; *lv = *(uint4*)l;
}
static __device__ __forceinline__ void store_split2(bf16* Ch, bf16* Cl, long off, float x, float y) {
    __align__(4) bf16 h[2] = {__float2bfloat16(x), __float2bfloat16(y)};
    __align__(4) bf16 l[2] = {__float2bfloat16(x - __bfloat162float(h[0])),
                              __float2bfloat16(y - __bfloat162float(h[1]))};
    *(uint32_t*)(Ch + off) = *(uint32_t*)h;
    *(uint32_t*)(Cl + off) = *(uint32_t*)l;
}

// ---------------- scratch ----------------
__device__ bf16 g_qh[4194304], g_ql[4194304];
__device__ bf16 g_xh[4194304], g_xl[4194304];
__device__ bf16 g_wqh[1048576], g_wql[1048576];
__device__ bf16 g_wkh[1048576], g_wkl[1048576];
__device__ bf16 g_wvh[1048576], g_wvl[1048576];
__device__ bf16 g_woh[1048576], g_wol[1048576];
__device__ bf16 g_Qh[4194304], g_Ql[4194304];
__device__ bf16 g_Kh[4194304], g_Kl[4194304];
__device__ bf16 g_Vh[4194304], g_Vl[4194304];
__device__ bf16 g_Vth[4194304], g_Vtl[4194304];  // [bh][64 d][2048 tok]
__device__ bf16 g_Bh[4194304], g_Bl[4194304];
__device__ float g_rowsum[65536];
__device__ float g_attn[134217728];

// ---------------- fp32 -> bf16 hi/lo ----------------
__global__ __launch_bounds__(256) void cvt_split(
    const float* __restrict__ src, bf16* __restrict__ h, bf16* __restrict__ l, int n4) {
    int i = blockIdx.x * 256 + threadIdx.x;
    if (i >= n4) return;
    float4 v = ((const float4*)src)[i];
    float f[4] = {v.x, v.y, v.z, v.w};
    __align__(8) bf16 hv[4], lv[4];
#pragma unroll
    for (int j = 0; j < 4; j++) {
        hv[j] = __float2bfloat16(f[j]);
        lv[j] = __float2bfloat16(f[j] - __bfloat162float(hv[j]));
    }
    ((uint2*)h)[i] = *(uint2*)hv;
    ((uint2*)l)[i] = *(uint2*)lv;
}

// ---------------------------------------------------------------------------
// hgemm: C[m,n] = sum_k A[m,k] B[n,k] + bias[n], A/B bf16 hi+lo, 3-product.
// 128x128 tile, BK=32, cp.async double-buffered. smem tiles stride 40 bf16.
// smem: buf{0,1} x {Ah,Al,Bh,Bl} tiles of 10240B -> 81920B
// ---------------------------------------------------------------------------
__global__ __launch_bounds__(256) void hgemm(
    const bf16* __restrict__ Ah, const bf16* __restrict__ Al,
    const bf16* __restrict__ Bh, const bf16* __restrict__ Bl,
    const float* __restrict__ bias, float* __restrict__ Cf,
    bf16* __restrict__ Ch, bf16* __restrict__ Cl,
    int K, int lda, int ldb, int ldc)
{
    extern __shared__ char sm[];
    uint32_t sb = smem_u32(sm);
    int t = threadIdx.x, lane = t & 31, wid = t >> 5;
    int wm = wid & 3, wn = wid >> 2;
    long m0 = blockIdx.y * 128, n0 = blockIdx.x * 128;

    const bf16* g0 = Ah + m0 * lda;
    const bf16* g1 = Al + m0 * lda;
    const bf16* g2 = Bh + n0 * ldb;
    const bf16* g3 = Bl + n0 * ldb;

#define G_ISSUE(c_, buf_) do {                                                  \
    int _c = (c_); uint32_t _bs = sb + (buf_) * 40960;                          \
    _Pragma("unroll")                                                           \
    for (int i = 0; i < 8; i++) {                                               \
        const int tile = i >> 1;                                                \
        int w = t + 256 * (i & 1);                                              \
        int row = w >> 2, sg = w & 3;                                           \
        const bf16* gp = (tile == 0 ? g0 : tile == 1 ? g1 : tile == 2 ? g2 : g3)\
            + (long)row * (tile < 2 ? lda : ldb) + _c * 32 + sg * 8;            \
        CP16(_bs + tile * 10240 + row * 80 + sg * 16, gp);                      \
    }                                                                           \
    CPCOMMIT();                                                                 \
} while (0)

    float acc[2][8][4] = {};
    int nc = K >> 5;
    G_ISSUE(0, 0);
    G_ISSUE(1, 1);
    for (int c = 0; c < nc; c++) {
        if (c + 1 < nc) { CPWAIT(1); } else { CPWAIT(0); }
        __syncthreads();
        uint32_t bAh = sb + (c & 1) * 40960, bAl = bAh + 10240;
        uint32_t bBh = bAh + 20480, bBl = bAh + 30720;
#pragma unroll
        for (int k0 = 0; k0 < 32; k0 += 16) {
            uint32_t ah[2][4], al[2][4], bhf[4][4], blf[4][4];
#pragma unroll
            for (int mt = 0; mt < 2; mt++) {
                ldsmA(ah[mt], bAh, wm * 32 + mt * 16, k0, 80, lane);
                ldsmA(al[mt], bAl, wm * 32 + mt * 16, k0, 80, lane);
            }
#pragma unroll
            for (int p = 0; p < 4; p++) {
                ldsmB(bhf[p], bBh, wn * 64 + p * 16, k0, 80, lane);
                ldsmB(blf[p], bBl, wn * 64 + p * 16, k0, 80, lane);
            }
#pragma unroll
            for (int mt = 0; mt < 2; mt++)
#pragma unroll
                for (int p = 0; p < 4; p++) {
                    mma3(acc[mt][p * 2],     ah[mt], al[mt], &bhf[p][0], &blf[p][0]);
                    mma3(acc[mt][p * 2 + 1], ah[mt], al[mt], &bhf[p][2], &blf[p][2]);
                }
        }
        __syncthreads();
        if (c + 2 < nc) G_ISSUE(c + 2, c & 1);
    }
#undef G_ISSUE

#pragma unroll
    for (int mt = 0; mt < 2; mt++)
#pragma unroll
        for (int nt = 0; nt < 8; nt++) {
            float* cc = acc[mt][nt];
            long r0 = m0 + wm * 32 + mt * 16 + (lane >> 2);
            int col = (int)n0 + wn * 64 + nt * 8 + 2 * (lane & 3);
            float b0 = bias[col], b1 = bias[col + 1];
            float f0 = cc[0] + b0, f1 = cc[1] + b1, f2 = cc[2] + b0, f3 = cc[3] + b1;
            if (Cf) {
                *(float2*)(Cf + r0 * ldc + col) = make_float2(f0, f1);
                *(float2*)(Cf + (r0 + 8) * ldc + col) = make_float2(f2, f3);
            }
            if (Ch) {
                store_split2(Ch, Cl, r0 * ldc + col, f0, f1);
                store_split2(Ch, Cl, (r0 + 8) * ldc + col, f2, f3);
            }
        }
}

// ---------------------------------------------------------------------------
// vtrans: V split [4096 tok,1024] -> per (b,h): [64 d][2048 tok]
// ---------------------------------------------------------------------------
__global__ __launch_bounds__(256) void vtrans(
    const bf16* __restrict__ Vh, const bf16* __restrict__ Vl,
    bf16* __restrict__ Th, bf16* __restrict__ Tl) {
    __shared__ bf16 sh[64][72], sl[64][72];
    int t = threadIdx.x, tt = blockIdx.x, bh = blockIdx.y;
    int b = bh >> 4, h = bh & 15;
    const bf16* srch = Vh + ((long)b * 2048 + tt * 64) * 1024 + h * 64;
    const bf16* srcl = Vl + ((long)b * 2048 + tt * 64) * 1024 + h * 64;
#pragma unroll
    for (int i = 0; i < 2; i++) {
        int s = t + 256 * i, row = s >> 3, seg = s & 7;
        *(uint4*)&sh[row][seg * 8] = *(const uint4*)(srch + (long)row * 1024 + seg * 8);
        *(uint4*)&sl[row][seg * 8] = *(const uint4*)(srcl + (long)row * 1024 + seg * 8);
    }
    __syncthreads();
    bf16* dh = Th + (long)bh * 64 * 2048 + tt * 64;
    bf16* dl = Tl + (long)bh * 64 * 2048 + tt * 64;
#pragma unroll
    for (int i = 0; i < 2; i++) {
        int s = t + 256 * i, d = s >> 3, seg = s & 7;
        __align__(16) bf16 th[8], tl[8];
#pragma unroll
        for (int j = 0; j < 8; j++) { th[j] = sh[seg * 8 + j][d]; tl[j] = sl[seg * 8 + j][d]; }
        *(uint4*)(dh + (long)d * 2048 + seg * 8) = *(uint4*)th;
        *(uint4*)(dl + (long)d * 2048 + seg * 8) = *(uint4*)tl;
    }
}

// ---------------------------------------------------------------------------
// hscores: E = exp(Q K^T + (1-mask)*NEG), rowsum. CTA: 128 q x 2048 k.
// smem: Qh@0 Ql@18432 Kh@36864 Kl@55296 (stride 72 bf16) msk@73728 part@74240
// ---------------------------------------------------------------------------
__global__ __launch_bounds__(256) void hscores(
    const bf16* __restrict__ Qh, const bf16* __restrict__ Ql,
    const bf16* __restrict__ Kh, const bf16* __restrict__ Kl,
    const float* __restrict__ mask, float* __restrict__ E, float* __restrict__ rowsum)
{
    extern __shared__ char sm[];
    uint32_t sb = smem_u32(sm);
    int t = threadIdx.x, lane = t & 31, wid = t >> 5;
    int wm = wid & 3, wn = wid >> 2;
    int qt = blockIdx.x, bh = blockIdx.y;
    int b = bh >> 4, h = bh & 15;

    const bf16* qh = Qh + ((long)b * 2048 + qt * 128) * 1024 + h * 64;
    const bf16* ql = Ql + ((long)b * 2048 + qt * 128) * 1024 + h * 64;
    const bf16* kh = Kh + (long)b * 2048 * 1024 + h * 64;
    const bf16* kl = Kl + (long)b * 2048 * 1024 + h * 64;
    float* Ebh = E + ((long)bh * 2048 + qt * 128) * 2048;
    const float* mrow = mask + (long)b * 2048;
    float* msk = (float*)(sm + 73728);
    float* part = (float*)(sm + 74240);

    // Q tiles (hi@0, lo@18432)
#pragma unroll
    for (int i = 0; i < 8; i++) {
        const int tile = i >> 2;
        int w = t + 256 * (i & 3);
        int row = w >> 3, sg = w & 7;
        const bf16* src = (tile ? ql : qh) + (long)row * 1024 + sg * 8;
        *(uint4*)(sm + tile * 18432 + row * 144 + sg * 16) = *(const uint4*)src;
    }

    float rs[4] = {0.f, 0.f, 0.f, 0.f};

    for (int kt = 0; kt < 16; kt++) {
        if (t < 128) msk[t] = (1.0f - mrow[kt * 128 + t]) * (-1e9f);
#pragma unroll
        for (int i = 0; i < 8; i++) {
            const int tile = i >> 2;
            int w = t + 256 * (i & 3);
            int row = w >> 3, sg = w & 7;
            const bf16* src = (tile ? kl : kh) + (long)(kt * 128 + row) * 1024 + sg * 8;
            *(uint4*)(sm + 36864 + tile * 18432 + row * 144 + sg * 16) = *(const uint4*)src;
        }
        __syncthreads();

        float acc[2][8][4] = {};
#pragma unroll
        for (int k0 = 0; k0 < 64; k0 += 16) {
            uint32_t ah[2][4], al[2][4], bhf[4][4], blf[4][4];
#pragma unroll
            for (int mt = 0; mt < 2; mt++) {
                ldsmA(ah[mt], sb,         wm * 32 + mt * 16, k0, 144, lane);
                ldsmA(al[mt], sb + 18432, wm * 32 + mt * 16, k0, 144, lane);
            }
#pragma unroll
            for (int p = 0; p < 4; p++) {
                ldsmB(bhf[p], sb + 36864, wn * 64 + p * 16, k0, 144, lane);
                ldsmB(blf[p], sb + 55296, wn * 64 + p * 16, k0, 144, lane);
            }
#pragma unroll
            for (int mt = 0; mt < 2; mt++)
#pragma unroll
                for (int p = 0; p < 4; p++) {
                    mma3(acc[mt][p * 2],     ah[mt], al[mt], &bhf[p][0], &blf[p][0]);
                    mma3(acc[mt][p * 2 + 1], ah[mt], al[mt], &bhf[p][2], &blf[p][2]);
                }
        }

        // epilogue: exp + mask + store + rowsum
#pragma unroll
        for (int mt = 0; mt < 2; mt++)
#pragma unroll
            for (int nt = 0; nt < 8; nt++) {
                float* cc = acc[mt][nt];
                int r0 = wm * 32 + mt * 16 + (lane >> 2);
                int cl = wn * 64 + nt * 8 + 2 * (lane & 3);
                float m0v = msk[cl], m1v = msk[cl + 1];
                float e0 = __expf(cc[0] + m0v), e1 = __expf(cc[1] + m1v);
                float e2 = __expf(cc[2] + m0v), e3 = __expf(cc[3] + m1v);
                rs[mt * 2 + 0] += e0 + e1;
                rs[mt * 2 + 1] += e2 + e3;
                *(float2*)(Ebh + (long)r0 * 2048 + kt * 128 + cl) = make_float2(e0, e1);
                *(float2*)(Ebh + (long)(r0 + 8) * 2048 + kt * 128 + cl) = make_float2(e2, e3);
            }
        __syncthreads();
    }

    // rowsum: quad-reduce then combine the two n-warps
#pragma unroll
    for (int i = 0; i < 4; i++) {
        rs[i] += __shfl_xor_sync(0xffffffffu, rs[i], 1);
        rs[i] += __shfl_xor_sync(0xffffffffu, rs[i], 2);
    }
    if ((lane & 3) == 0) {
#pragma unroll
        for (int mt = 0; mt < 2; mt++)
#pragma unroll
            for (int hf = 0; hf < 2; hf++)
                part[wn * 128 + wm * 32 + mt * 16 + hf * 8 + (lane >> 2)] = rs[mt * 2 + hf];
    }
    __syncthreads();
    if (t < 128)
        rowsum[(long)bh * 2048 + qt * 128 + t] = part[t] + part[128 + t];
}

// ---------------------------------------------------------------------------
// hattnv: attn = E/rowsum (write back in place), O = attn @ V -> Bh/Bl split.
// smem: Ph@0 Pl@34816 (128x136 bf16) Vh@69632 Vl@87040 (64x136 bf16) = 104448B
// ---------------------------------------------------------------------------
__global__ __launch_bounds__(256) void hattnv(
    float* __restrict__ E,
    const bf16* __restrict__ Vth, const bf16* __restrict__ Vtl,
    const float* __restrict__ rowsum,
    bf16* __restrict__ Bh, bf16* __restrict__ Bl)
{
    extern __shared__ char sm[];
    uint32_t sb = smem_u32(sm);
    int t = threadIdx.x, lane = t & 31, wid = t >> 5;
    int wm = wid & 3, wn = wid >> 2;
    int qt = blockIdx.x, bh = blockIdx.y;
    int b = bh >> 4, h = bh & 15;

    float* Ebh = E + ((long)bh * 2048 + qt * 128) * 2048;
    const bf16* vth = Vth + (long)bh * 64 * 2048;
    const bf16* vtl = Vtl + (long)bh * 64 * 2048;

    int crow = t >> 1, chalf = t & 1;
    float inv = 1.0f / rowsum[(long)bh * 2048 + qt * 128 + crow];

    float acc[2][4][4] = {};

    for (int kt = 0; kt < 16; kt++) {
        // V^T tiles (hi@69632, lo@87040): 64 rows x 128 k, stride 136 bf16
#pragma unroll
        for (int i = 0; i < 8; i++) {
            const int tile = i >> 2;
            int w = t + 256 * (i & 3);
            int row = w >> 4, sg = w & 15;
            const bf16* src = (tile ? vtl : vth) + (long)row * 2048 + kt * 128 + sg * 8;
            *(uint4*)(sm + 69632 + tile * 17408 + row * 272 + sg * 16) = *(const uint4*)src;
        }
        // P: read E, scale, write attn back, split -> smem (128x136 bf16)
        {
            float* gp = Ebh + (long)crow * 2048 + kt * 128 + chalf * 64;
            char* ph = sm + crow * 272 + chalf * 128;
            char* pl = sm + 34816 + crow * 272 + chalf * 128;
#pragma unroll
            for (int j = 0; j < 8; j++) {
                float4 v0 = *(const float4*)(gp + j * 8);
                float4 v1 = *(const float4*)(gp + j * 8 + 4);
                v0.x *= inv; v0.y *= inv; v0.z *= inv; v0.w *= inv;
                v1.x *= inv; v1.y *= inv; v1.z *= inv; v1.w *= inv;
                *(float4*)(gp + j * 8) = v0;
                *(float4*)(gp + j * 8 + 4) = v1;
                float f[8] = {v0.x, v0.y, v0.z, v0.w, v1.x, v1.y, v1.z, v1.w};
                uint4 hv, lv;
                split8(f, &hv, &lv);
                *(uint4*)(ph + j * 16) = hv;
                *(uint4*)(pl + j * 16) = lv;
            }
        }
        __syncthreads();

#pragma unroll
        for (int k0 = 0; k0 < 128; k0 += 16) {
            uint32_t ah[2][4], al[2][4], bhf[2][4], blf[2][4];
#pragma unroll
            for (int mt = 0; mt < 2; mt++) {
                ldsmA(ah[mt], sb,         wm * 32 + mt * 16, k0, 272, lane);
                ldsmA(al[mt], sb + 34816, wm * 32 + mt * 16, k0, 272, lane);
            }
#pragma unroll
            for (int p = 0; p < 2; p++) {
                ldsmB(bhf[p], sb + 69632, wn * 32 + p * 16, k0, 272, lane);
                ldsmB(blf[p], sb + 87040, wn * 32 + p * 16, k0, 272, lane);
            }
#pragma unroll
            for (int mt = 0; mt < 2; mt++)
#pragma unroll
                for (int p = 0; p < 2; p++) {
                    mma3(acc[mt][p * 2],     ah[mt], al[mt], &bhf[p][0], &blf[p][0]);
                    mma3(acc[mt][p * 2 + 1], ah[mt], al[mt], &bhf[p][2], &blf[p][2]);
                }
        }
        __syncthreads();
    }

    // write blended split [b, q, h*64+d]
#pragma unroll
    for (int mt = 0; mt < 2; mt++)
#pragma unroll
        for (int nt = 0; nt < 4; nt++) {
            float* cc = acc[mt][nt];
            long r0 = (long)b * 2048 + qt * 128 + wm * 32 + mt * 16 + (lane >> 2);
            int col = h * 64 + wn * 32 + nt * 8 + 2 * (lane & 3);
            store_split2(Bh, Bl, r0 * 1024 + col, cc[0], cc[1]);
            store_split2(Bh, Bl, (r0 + 8) * 1024 + col, cc[2], cc[3]);
        }
}

// ===========================================================================
extern "C" void kernel_launch(void* const* d_in, const int* in_sizes, int n_in,
                              void* d_out, int out_size) {
    (void)in_sizes; (void)n_in;
    const float* query        = (const float*)d_in[0];
    const float* input_embeds = (const float*)d_in[1];
    const float* mask         = (const float*)d_in[2];
    const float* wq_w = (const float*)d_in[3];
    const float* wq_b = (const float*)d_in[4];
    const float* wk_w = (const float*)d_in[5];
    const float* wk_b = (const float*)d_in[6];
    const float* wv_w = (const float*)d_in[7];
    const float* wv_b = (const float*)d_in[8];
    const float* wo_w = (const float*)d_in[9];
    const float* wo_b = (const float*)d_in[10];
    float* out = (float*)d_out;

    bf16 *qh, *ql, *xh, *xl, *wqh, *wql, *wkh, *wkl, *wvh, *wvl, *woh, *wol;
    bf16 *Qh, *Ql, *Kh, *Kl, *Vh, *Vl, *Vth, *Vtl, *Bh, *Bl;
    float *rowsum, *attn_scratch;
    cudaGetSymbolAddress((void**)&qh, g_qh);   cudaGetSymbolAddress((void**)&ql, g_ql);
    cudaGetSymbolAddress((void**)&xh, g_xh);   cudaGetSymbolAddress((void**)&xl, g_xl);
    cudaGetSymbolAddress((void**)&wqh, g_wqh); cudaGetSymbolAddress((void**)&wql, g_wql);
    cudaGetSymbolAddress((void**)&wkh, g_wkh); cudaGetSymbolAddress((void**)&wkl, g_wkl);
    cudaGetSymbolAddress((void**)&wvh, g_wvh); cudaGetSymbolAddress((void**)&wvl, g_wvl);
    cudaGetSymbolAddress((void**)&woh, g_woh); cudaGetSymbolAddress((void**)&wol, g_wol);
    cudaGetSymbolAddress((void**)&Qh, g_Qh);   cudaGetSymbolAddress((void**)&Ql, g_Ql);
    cudaGetSymbolAddress((void**)&Kh, g_Kh);   cudaGetSymbolAddress((void**)&Kl, g_Kl);
    cudaGetSymbolAddress((void**)&Vh, g_Vh);   cudaGetSymbolAddress((void**)&Vl, g_Vl);
    cudaGetSymbolAddress((void**)&Vth, g_Vth); cudaGetSymbolAddress((void**)&Vtl, g_Vtl);
    cudaGetSymbolAddress((void**)&Bh, g_Bh);   cudaGetSymbolAddress((void**)&Bl, g_Bl);
    cudaGetSymbolAddress((void**)&rowsum, g_rowsum);
    cudaGetSymbolAddress((void**)&attn_scratch, g_attn);

    const long OUT_E = 4194304L, ATTN_E = 134217728L;
    float* attn = ((long)out_size >= OUT_E + ATTN_E) ? (out + OUT_E) : attn_scratch;

    const int SM_GEMM = 81920;
    const int SM_SCOR = 75264;
    const int SM_ATTV = 104448;
    cudaFuncSetAttribute(hgemm,   cudaFuncAttributeMaxDynamicSharedMemorySize, SM_GEMM);
    cudaFuncSetAttribute(hscores, cudaFuncAttributeMaxDynamicSharedMemorySize, SM_SCOR);
    cudaFuncSetAttribute(hattnv,  cudaFuncAttributeMaxDynamicSharedMemorySize, SM_ATTV);

    cvt_split<<<4096, 256>>>(query,        qh, ql, 1048576);
    cvt_split<<<4096, 256>>>(input_embeds, xh, xl, 1048576);
    cvt_split<<<1024, 256>>>(wq_w, wqh, wql, 262144);
    cvt_split<<<1024, 256>>>(wk_w, wkh, wkl, 262144);
    cvt_split<<<1024, 256>>>(wv_w, wvh, wvl, 262144);
    cvt_split<<<1024, 256>>>(wo_w, woh, wol, 262144);

    dim3 gP(8, 32);
    hgemm<<<gP, 256, SM_GEMM>>>(qh, ql, wqh, wql, wq_b, nullptr, Qh, Ql, 1024, 1024, 1024, 1024);
    hgemm<<<gP, 256, SM_GEMM>>>(xh, xl, wkh, wkl, wk_b, nullptr, Kh, Kl, 1024, 1024, 1024, 1024);
    hgemm<<<gP, 256, SM_GEMM>>>(xh, xl, wvh, wvl, wv_b, nullptr, Vh, Vl, 1024, 1024, 1024, 1024);

    vtrans<<<dim3(32, 32), 256>>>(Vh, Vl, Vth, Vtl);

    dim3 gS(16, 32);
    hscores<<<gS, 256, SM_SCOR>>>(Qh, Ql, Kh, Kl, mask, attn, rowsum);
    hattnv<<<gS, 256, SM_ATTV>>>(attn, Vth, Vtl, rowsum, Bh, Bl);

    hgemm<<<gP, 256, SM_GEMM>>>(Bh, Bl, woh, wol, wo_b, out, nullptr, nullptr, 1024, 1024, 1024, 1024);
}

// round 6
// speedup vs baseline: 2.2910x; 1.6402x over previous
#include <cuda_runtime.h>
#include <cuda_bf16.h>
#include <cstdint>

typedef __nv_bfloat16 bf16;

// ---------------------------------------------------------------------------
static __device__ __forceinline__ uint32_t smem_u32(const void* p) {
    uint32_t a;
    asm("{ .reg .u64 t; cvta.to.shared.u64 t, %1; cvt.u32.u64 %0, t; }" : "=r"(a) : "l"(p));
    return a;
}
static __device__ __forceinline__ void mma16816(float* c, const uint32_t* a, const uint32_t* b) {
    asm volatile("mma.sync.aligned.m16n8k16.row.col.f32.bf16.bf16.f32 "
        "{%0,%1,%2,%3}, {%4,%5,%6,%7}, {%8,%9}, {%0,%1,%2,%3};"
        : "+f"(c[0]), "+f"(c[1]), "+f"(c[2]), "+f"(c[3])
        : "r"(a[0]), "r"(a[1]), "r"(a[2]), "r"(a[3]), "r"(b[0]), "r"(b[1]));
}
static __device__ __forceinline__ void mma3(float* c, const uint32_t* ah, const uint32_t* al,
                                            const uint32_t* bh, const uint32_t* bl) {
    mma16816(c, ah, bh); mma16816(c, ah, bl); mma16816(c, al, bh);
}
static __device__ __forceinline__ void ldsm4(uint32_t* r, uint32_t a) {
    asm volatile("ldmatrix.sync.aligned.m8n8.x4.shared.b16 {%0,%1,%2,%3}, [%4];"
        : "=r"(r[0]), "=r"(r[1]), "=r"(r[2]), "=r"(r[3]) : "r"(a));
}
static __device__ __forceinline__ void ldsmA(uint32_t* r, uint32_t base, int m0, int k0, int sbytes, int lane) {
    ldsm4(r, base + (uint32_t)((m0 + (lane & 7) + ((lane >> 3) & 1) * 8) * sbytes
                               + (k0 + ((lane >> 4) << 3)) * 2));
}
static __device__ __forceinline__ void ldsmB(uint32_t* r, uint32_t base, int n0, int k0, int sbytes, int lane) {
    ldsm4(r, base + (uint32_t)((n0 + (lane & 7) + ((lane >> 4) << 3)) * sbytes
                               + (k0 + (((lane >> 3) & 1) << 3)) * 2));
}
#define CP16(sm_, gp_) asm volatile("cp.async.cg.shared.global [%0], [%1], 16;" :: "r"(sm_), "l"(gp_))
#define CPCOMMIT()     asm volatile("cp.async.commit_group;")
#define CPWAIT(n)      asm volatile("cp.async.wait_group %0;" :: "n"(n))

static __device__ __forceinline__ void split8(const float* f, uint4* hv, uint4* lv) {
    __align__(16) bf16 h[8], l[8];
#pragma unroll
    for (int j = 0; j < 8; j++) {
        h[j] = __float2bfloat16(f[j]);
        l[j] = __float2bfloat16(f[j] - __bfloat162float(h[j]));
    }
    *hv = *(uint4*)h; *lv = *(uint4*)l;
}
static __device__ __forceinline__ void store_split2(bf16* Ch, bf16* Cl, long off, float x, float y) {
    __align__(4) bf16 h[2] = {__float2bfloat16(x), __float2bfloat16(y)};
    __align__(4) bf16 l[2] = {__float2bfloat16(x - __bfloat162float(h[0])),
                              __float2bfloat16(y - __bfloat162float(h[1]))};
    *(uint32_t*)(Ch + off) = *(uint32_t*)h;
    *(uint32_t*)(Cl + off) = *(uint32_t*)l;
}
static __device__ __forceinline__ void smem_split2(char* ph, char* pl, float x, float y) {
    __align__(4) bf16 h[2] = {__float2bfloat16(x), __float2bfloat16(y)};
    __align__(4) bf16 l[2] = {__float2bfloat16(x - __bfloat162float(h[0])),
                              __float2bfloat16(y - __bfloat162float(h[1]))};
    *(uint32_t*)ph = *(uint32_t*)h;
    *(uint32_t*)pl = *(uint32_t*)l;
}

// ---------------- scratch ----------------
__device__ bf16 g_qh[4194304], g_ql[4194304];
__device__ bf16 g_xh[4194304], g_xl[4194304];
__device__ bf16 g_wqh[1048576], g_wql[1048576];
__device__ bf16 g_wkh[1048576], g_wkl[1048576];
__device__ bf16 g_wvh[1048576], g_wvl[1048576];
__device__ bf16 g_woh[1048576], g_wol[1048576];
__device__ bf16 g_Qh[4194304], g_Ql[4194304];
__device__ bf16 g_Kh[4194304], g_Kl[4194304];
__device__ bf16 g_Vh[4194304], g_Vl[4194304];
__device__ bf16 g_Vth[4194304], g_Vtl[4194304];  // [bh][64 d][2048 tok]
__device__ bf16 g_Bh[4194304], g_Bl[4194304];
__device__ float g_attn[134217728];              // fallback if attn not in d_out

// ---------------- fp32 -> bf16 hi/lo ----------------
__global__ __launch_bounds__(256) void cvt_split(
    const float* __restrict__ src, bf16* __restrict__ h, bf16* __restrict__ l, int n4) {
    int i = blockIdx.x * 256 + threadIdx.x;
    if (i >= n4) return;
    float4 v = ((const float4*)src)[i];
    float f[4] = {v.x, v.y, v.z, v.w};
    __align__(8) bf16 hv[4], lv[4];
#pragma unroll
    for (int j = 0; j < 4; j++) {
        hv[j] = __float2bfloat16(f[j]);
        lv[j] = __float2bfloat16(f[j] - __bfloat162float(hv[j]));
    }
    ((uint2*)h)[i] = *(uint2*)hv;
    ((uint2*)l)[i] = *(uint2*)lv;
}

// ---------------------------------------------------------------------------
// hgemm: C = A·B^T + bias (bf16 hi/lo, 3-product), 128x128, cp.async pipelined
// ---------------------------------------------------------------------------
__global__ __launch_bounds__(256) void hgemm(
    const bf16* __restrict__ Ah, const bf16* __restrict__ Al,
    const bf16* __restrict__ Bh, const bf16* __restrict__ Bl,
    const float* __restrict__ bias, float* __restrict__ Cf,
    bf16* __restrict__ Ch, bf16* __restrict__ Cl,
    int K, int lda, int ldb, int ldc)
{
    extern __shared__ char sm[];
    uint32_t sb = smem_u32(sm);
    int t = threadIdx.x, lane = t & 31, wid = t >> 5;
    int wm = wid & 3, wn = wid >> 2;
    long m0 = blockIdx.y * 128, n0 = blockIdx.x * 128;

    const bf16* g0 = Ah + m0 * lda;
    const bf16* g1 = Al + m0 * lda;
    const bf16* g2 = Bh + n0 * ldb;
    const bf16* g3 = Bl + n0 * ldb;

#define G_ISSUE(c_, buf_) do {                                                  \
    int _c = (c_); uint32_t _bs = sb + (buf_) * 40960;                          \
    _Pragma("unroll")                                                           \
    for (int i = 0; i < 8; i++) {                                               \
        const int tile = i >> 1;                                                \
        int w = t + 256 * (i & 1);                                              \
        int row = w >> 2, sg = w & 3;                                           \
        const bf16* gp = (tile == 0 ? g0 : tile == 1 ? g1 : tile == 2 ? g2 : g3)\
            + (long)row * (tile < 2 ? lda : ldb) + _c * 32 + sg * 8;            \
        CP16(_bs + tile * 10240 + row * 80 + sg * 16, gp);                      \
    }                                                                           \
    CPCOMMIT();                                                                 \
} while (0)

    float acc[2][8][4] = {};
    int nc = K >> 5;
    G_ISSUE(0, 0);
    G_ISSUE(1, 1);
    for (int c = 0; c < nc; c++) {
        if (c + 1 < nc) { CPWAIT(1); } else { CPWAIT(0); }
        __syncthreads();
        uint32_t bAh = sb + (c & 1) * 40960, bAl = bAh + 10240;
        uint32_t bBh = bAh + 20480, bBl = bAh + 30720;
#pragma unroll
        for (int k0 = 0; k0 < 32; k0 += 16) {
            uint32_t ah[2][4], al[2][4], bhf[4][4], blf[4][4];
#pragma unroll
            for (int mt = 0; mt < 2; mt++) {
                ldsmA(ah[mt], bAh, wm * 32 + mt * 16, k0, 80, lane);
                ldsmA(al[mt], bAl, wm * 32 + mt * 16, k0, 80, lane);
            }
#pragma unroll
            for (int p = 0; p < 4; p++) {
                ldsmB(bhf[p], bBh, wn * 64 + p * 16, k0, 80, lane);
                ldsmB(blf[p], bBl, wn * 64 + p * 16, k0, 80, lane);
            }
#pragma unroll
            for (int mt = 0; mt < 2; mt++)
#pragma unroll
                for (int p = 0; p < 4; p++) {
                    mma3(acc[mt][p * 2],     ah[mt], al[mt], &bhf[p][0], &blf[p][0]);
                    mma3(acc[mt][p * 2 + 1], ah[mt], al[mt], &bhf[p][2], &blf[p][2]);
                }
        }
        __syncthreads();
        if (c + 2 < nc) G_ISSUE(c + 2, c & 1);
    }
#undef G_ISSUE

#pragma unroll
    for (int mt = 0; mt < 2; mt++)
#pragma unroll
        for (int nt = 0; nt < 8; nt++) {
            float* cc = acc[mt][nt];
            long r0 = m0 + wm * 32 + mt * 16 + (lane >> 2);
            int col = (int)n0 + wn * 64 + nt * 8 + 2 * (lane & 3);
            float b0 = bias[col], b1 = bias[col + 1];
            float f0 = cc[0] + b0, f1 = cc[1] + b1, f2 = cc[2] + b0, f3 = cc[3] + b1;
            if (Cf) {
                *(float2*)(Cf + r0 * ldc + col) = make_float2(f0, f1);
                *(float2*)(Cf + (r0 + 8) * ldc + col) = make_float2(f2, f3);
            }
            if (Ch) {
                store_split2(Ch, Cl, r0 * ldc + col, f0, f1);
                store_split2(Ch, Cl, (r0 + 8) * ldc + col, f2, f3);
            }
        }
}

// ---------------------------------------------------------------------------
// vtrans: V split [4096 tok,1024] -> per (b,h): [64 d][2048 tok]
// ---------------------------------------------------------------------------
__global__ __launch_bounds__(256) void vtrans(
    const bf16* __restrict__ Vh, const bf16* __restrict__ Vl,
    bf16* __restrict__ Th, bf16* __restrict__ Tl) {
    __shared__ bf16 sh[64][72], sl[64][72];
    int t = threadIdx.x, tt = blockIdx.x, bh = blockIdx.y;
    int b = bh >> 4, h = bh & 15;
    const bf16* srch = Vh + ((long)b * 2048 + tt * 64) * 1024 + h * 64;
    const bf16* srcl = Vl + ((long)b * 2048 + tt * 64) * 1024 + h * 64;
#pragma unroll
    for (int i = 0; i < 2; i++) {
        int s = t + 256 * i, row = s >> 3, seg = s & 7;
        *(uint4*)&sh[row][seg * 8] = *(const uint4*)(srch + (long)row * 1024 + seg * 8);
        *(uint4*)&sl[row][seg * 8] = *(const uint4*)(srcl + (long)row * 1024 + seg * 8);
    }
    __syncthreads();
    bf16* dh = Th + (long)bh * 64 * 2048 + tt * 64;
    bf16* dl = Tl + (long)bh * 64 * 2048 + tt * 64;
#pragma unroll
    for (int i = 0; i < 2; i++) {
        int s = t + 256 * i, d = s >> 3, seg = s & 7;
        __align__(16) bf16 th[8], tl[8];
#pragma unroll
        for (int j = 0; j < 8; j++) { th[j] = sh[seg * 8 + j][d]; tl[j] = sl[seg * 8 + j][d]; }
        *(uint4*)(dh + (long)d * 2048 + seg * 8) = *(uint4*)th;
        *(uint4*)(dl + (long)d * 2048 + seg * 8) = *(uint4*)tl;
    }
}

// ---------------------------------------------------------------------------
// fused_attn: per CTA (128 q rows, one bh):
//   pass A: rowsum of exp(QK^T + maskadd)           (no stores)
//   pass B: recompute scores, write attn = e*inv, P->smem, O += P·V
// smem layout (bytes):
//   Q hi @0, Q lo @18432                (128x(64+8) bf16, stride 144)
//   K hi @36864, K lo @55296            (stride 144)   } overlapped with
//   P hi @36864, P lo @71680            (128x136 bf16, stride 272)
//   V hi @106496, V lo @123904          (64x136 bf16, stride 272)
//   msk @141312 (128 f), part @141824 (256 f), inv @142848 (128 f)
// total 143360
// ---------------------------------------------------------------------------
__global__ __launch_bounds__(256, 1) void fused_attn(
    const bf16* __restrict__ Qh, const bf16* __restrict__ Ql,
    const bf16* __restrict__ Kh, const bf16* __restrict__ Kl,
    const bf16* __restrict__ Vth, const bf16* __restrict__ Vtl,
    const float* __restrict__ mask,
    float* __restrict__ A,           // attn out [bh][2048 q][2048 k]
    bf16* __restrict__ Bh, bf16* __restrict__ Bl)
{
    extern __shared__ char sm[];
    uint32_t sb = smem_u32(sm);
    int t = threadIdx.x, lane = t & 31, wid = t >> 5;
    int wm = wid & 3, wn = wid >> 2;
    int qt = blockIdx.x, bh = blockIdx.y;
    int b = bh >> 4, h = bh & 15;

    const bf16* qh = Qh + ((long)b * 2048 + qt * 128) * 1024 + h * 64;
    const bf16* ql = Ql + ((long)b * 2048 + qt * 128) * 1024 + h * 64;
    const bf16* kh = Kh + (long)b * 2048 * 1024 + h * 64;
    const bf16* kl = Kl + (long)b * 2048 * 1024 + h * 64;
    const bf16* vth = Vth + (long)bh * 64 * 2048;
    const bf16* vtl = Vtl + (long)bh * 64 * 2048;
    float* Abh = A + ((long)bh * 2048 + qt * 128) * 2048;
    const float* mrow = mask + (long)b * 2048;

    float* msk  = (float*)(sm + 141312);
    float* part = (float*)(sm + 141824);
    float* invs = (float*)(sm + 142848);

    // Q tiles (hi@0, lo@18432), stride 144
#pragma unroll
    for (int i = 0; i < 8; i++) {
        const int tile = i >> 2;
        int w = t + 256 * (i & 3);
        int row = w >> 3, sg = w & 7;
        const bf16* src = (tile ? ql : qh) + (long)row * 1024 + sg * 8;
        *(uint4*)(sm + tile * 18432 + row * 144 + sg * 16) = *(const uint4*)src;
    }

    // ---------------- pass A: rowsum only ----------------
    float rs[4] = {0.f, 0.f, 0.f, 0.f};
    for (int kt = 0; kt < 16; kt++) {
        if (t < 128) msk[t] = (1.0f - mrow[kt * 128 + t]) * (-1e9f);
#pragma unroll
        for (int i = 0; i < 8; i++) {
            const int tile = i >> 2;
            int w = t + 256 * (i & 3);
            int row = w >> 3, sg = w & 7;
            const bf16* src = (tile ? kl : kh) + (long)(kt * 128 + row) * 1024 + sg * 8;
            *(uint4*)(sm + 36864 + tile * 18432 + row * 144 + sg * 16) = *(const uint4*)src;
        }
        __syncthreads();

        float acc[2][8][4] = {};
#pragma unroll
        for (int k0 = 0; k0 < 64; k0 += 16) {
            uint32_t ah[2][4], al[2][4], bhf[4][4], blf[4][4];
#pragma unroll
            for (int mt = 0; mt < 2; mt++) {
                ldsmA(ah[mt], sb,         wm * 32 + mt * 16, k0, 144, lane);
                ldsmA(al[mt], sb + 18432, wm * 32 + mt * 16, k0, 144, lane);
            }
#pragma unroll
            for (int p = 0; p < 4; p++) {
                ldsmB(bhf[p], sb + 36864, wn * 64 + p * 16, k0, 144, lane);
                ldsmB(blf[p], sb + 55296, wn * 64 + p * 16, k0, 144, lane);
            }
#pragma unroll
            for (int mt = 0; mt < 2; mt++)
#pragma unroll
                for (int p = 0; p < 4; p++) {
                    mma3(acc[mt][p * 2],     ah[mt], al[mt], &bhf[p][0], &blf[p][0]);
                    mma3(acc[mt][p * 2 + 1], ah[mt], al[mt], &bhf[p][2], &blf[p][2]);
                }
        }
#pragma unroll
        for (int mt = 0; mt < 2; mt++)
#pragma unroll
            for (int nt = 0; nt < 8; nt++) {
                float* cc = acc[mt][nt];
                int cl = wn * 64 + nt * 8 + 2 * (lane & 3);
                float m0v = msk[cl], m1v = msk[cl + 1];
                rs[mt * 2 + 0] += __expf(cc[0] + m0v) + __expf(cc[1] + m1v);
                rs[mt * 2 + 1] += __expf(cc[2] + m0v) + __expf(cc[3] + m1v);
            }
        __syncthreads();
    }

    // reduce rowsum -> invs[128]
#pragma unroll
    for (int i = 0; i < 4; i++) {
        rs[i] += __shfl_xor_sync(0xffffffffu, rs[i], 1);
        rs[i] += __shfl_xor_sync(0xffffffffu, rs[i], 2);
    }
    if ((lane & 3) == 0) {
#pragma unroll
        for (int mt = 0; mt < 2; mt++)
#pragma unroll
            for (int hf = 0; hf < 2; hf++)
                part[wn * 128 + wm * 32 + mt * 16 + hf * 8 + (lane >> 2)] = rs[mt * 2 + hf];
    }
    __syncthreads();
    if (t < 128) invs[t] = 1.0f / (part[t] + part[128 + t]);
    __syncthreads();

    float invr[2][2];
#pragma unroll
    for (int mt = 0; mt < 2; mt++) {
        invr[mt][0] = invs[wm * 32 + mt * 16 + (lane >> 2)];
        invr[mt][1] = invs[wm * 32 + mt * 16 + 8 + (lane >> 2)];
    }

    // ---------------- pass B: recompute, write attn, O += P·V ----------------
    float oacc[2][4][4] = {};
    for (int kt = 0; kt < 16; kt++) {
        if (t < 128) msk[t] = (1.0f - mrow[kt * 128 + t]) * (-1e9f);
#pragma unroll
        for (int i = 0; i < 8; i++) {   // K tiles
            const int tile = i >> 2;
            int w = t + 256 * (i & 3);
            int row = w >> 3, sg = w & 7;
            const bf16* src = (tile ? kl : kh) + (long)(kt * 128 + row) * 1024 + sg * 8;
            *(uint4*)(sm + 36864 + tile * 18432 + row * 144 + sg * 16) = *(const uint4*)src;
        }
#pragma unroll
        for (int i = 0; i < 8; i++) {   // V^T tiles, stride 272
            const int tile = i >> 2;
            int w = t + 256 * (i & 3);
            int row = w >> 4, sg = w & 15;
            const bf16* src = (tile ? vtl : vth) + (long)row * 2048 + kt * 128 + sg * 8;
            *(uint4*)(sm + 106496 + tile * 17408 + row * 272 + sg * 16) = *(const uint4*)src;
        }
        __syncthreads();

        float acc[2][8][4] = {};
#pragma unroll
        for (int k0 = 0; k0 < 64; k0 += 16) {
            uint32_t ah[2][4], al[2][4], bhf[4][4], blf[4][4];
#pragma unroll
            for (int mt = 0; mt < 2; mt++) {
                ldsmA(ah[mt], sb,         wm * 32 + mt * 16, k0, 144, lane);
                ldsmA(al[mt], sb + 18432, wm * 32 + mt * 16, k0, 144, lane);
            }
#pragma unroll
            for (int p = 0; p < 4; p++) {
                ldsmB(bhf[p], sb + 36864, wn * 64 + p * 16, k0, 144, lane);
                ldsmB(blf[p], sb + 55296, wn * 64 + p * 16, k0, 144, lane);
            }
#pragma unroll
            for (int mt = 0; mt < 2; mt++)
#pragma unroll
                for (int p = 0; p < 4; p++) {
                    mma3(acc[mt][p * 2],     ah[mt], al[mt], &bhf[p][0], &blf[p][0]);
                    mma3(acc[mt][p * 2 + 1], ah[mt], al[mt], &bhf[p][2], &blf[p][2]);
                }
        }
        __syncthreads();   // done reading K smem; P overwrites it

        // epilogue: normalize, write attn, split P -> smem
#pragma unroll
        for (int mt = 0; mt < 2; mt++)
#pragma unroll
            for (int nt = 0; nt < 8; nt++) {
                float* cc = acc[mt][nt];
                int r0 = wm * 32 + mt * 16 + (lane >> 2);
                int cl = wn * 64 + nt * 8 + 2 * (lane & 3);
                float m0v = msk[cl], m1v = msk[cl + 1];
                float e0 = __expf(cc[0] + m0v) * invr[mt][0];
                float e1 = __expf(cc[1] + m1v) * invr[mt][0];
                float e2 = __expf(cc[2] + m0v) * invr[mt][1];
                float e3 = __expf(cc[3] + m1v) * invr[mt][1];
                *(float2*)(Abh + (long)r0 * 2048 + kt * 128 + cl)       = make_float2(e0, e1);
                *(float2*)(Abh + (long)(r0 + 8) * 2048 + kt * 128 + cl) = make_float2(e2, e3);
                smem_split2(sm + 36864 + r0 * 272 + cl * 2,
                            sm + 71680 + r0 * 272 + cl * 2, e0, e1);
                smem_split2(sm + 36864 + (r0 + 8) * 272 + cl * 2,
                            sm + 71680 + (r0 + 8) * 272 + cl * 2, e2, e3);
            }
        __syncthreads();

        // O += P · V^T  (P 128x128 @36864/71680 stride 272; V 64x128 @106496/123904)
#pragma unroll
        for (int k0 = 0; k0 < 128; k0 += 16) {
            uint32_t ah[2][4], al[2][4], bhf[2][4], blf[2][4];
#pragma unroll
            for (int mt = 0; mt < 2; mt++) {
                ldsmA(ah[mt], sb + 36864, wm * 32 + mt * 16, k0, 272, lane);
                ldsmA(al[mt], sb + 71680, wm * 32 + mt * 16, k0, 272, lane);
            }
#pragma unroll
            for (int p = 0; p < 2; p++) {
                ldsmB(bhf[p], sb + 106496, wn * 32 + p * 16, k0, 272, lane);
                ldsmB(blf[p], sb + 123904, wn * 32 + p * 16, k0, 272, lane);
            }
#pragma unroll
            for (int mt = 0; mt < 2; mt++)
#pragma unroll
                for (int p = 0; p < 2; p++) {
                    mma3(oacc[mt][p * 2],     ah[mt], al[mt], &bhf[p][0], &blf[p][0]);
                    mma3(oacc[mt][p * 2 + 1], ah[mt], al[mt], &bhf[p][2], &blf[p][2]);
                }
        }
        __syncthreads();
    }

    // write blended split [b, q, h*64+d]
#pragma unroll
    for (int mt = 0; mt < 2; mt++)
#pragma unroll
        for (int nt = 0; nt < 4; nt++) {
            float* cc = oacc[mt][nt];
            long r0 = (long)b * 2048 + qt * 128 + wm * 32 + mt * 16 + (lane >> 2);
            int col = h * 64 + wn * 32 + nt * 8 + 2 * (lane & 3);
            store_split2(Bh, Bl, r0 * 1024 + col, cc[0], cc[1]);
            store_split2(Bh, Bl, (r0 + 8) * 1024 + col, cc[2], cc[3]);
        }
}

// ===========================================================================
extern "C" void kernel_launch(void* const* d_in, const int* in_sizes, int n_in,
                              void* d_out, int out_size) {
    (void)in_sizes; (void)n_in;
    const float* query        = (const float*)d_in[0];
    const float* input_embeds = (const float*)d_in[1];
    const float* mask         = (const float*)d_in[2];
    const float* wq_w = (const float*)d_in[3];
    const float* wq_b = (const float*)d_in[4];
    const float* wk_w = (const float*)d_in[5];
    const float* wk_b = (const float*)d_in[6];
    const float* wv_w = (const float*)d_in[7];
    const float* wv_b = (const float*)d_in[8];
    const float* wo_w = (const float*)d_in[9];
    const float* wo_b = (const float*)d_in[10];
    float* out = (float*)d_out;

    bf16 *qh, *ql, *xh, *xl, *wqh, *wql, *wkh, *wkl, *wvh, *wvl, *woh, *wol;
    bf16 *Qh, *Ql, *Kh, *Kl, *Vh, *Vl, *Vth, *Vtl, *Bh, *Bl;
    float *attn_scratch;
    cudaGetSymbolAddress((void**)&qh, g_qh);   cudaGetSymbolAddress((void**)&ql, g_ql);
    cudaGetSymbolAddress((void**)&xh, g_xh);   cudaGetSymbolAddress((void**)&xl, g_xl);
    cudaGetSymbolAddress((void**)&wqh, g_wqh); cudaGetSymbolAddress((void**)&wql, g_wql);
    cudaGetSymbolAddress((void**)&wkh, g_wkh); cudaGetSymbolAddress((void**)&wkl, g_wkl);
    cudaGetSymbolAddress((void**)&wvh, g_wvh); cudaGetSymbolAddress((void**)&wvl, g_wvl);
    cudaGetSymbolAddress((void**)&woh, g_woh); cudaGetSymbolAddress((void**)&wol, g_wol);
    cudaGetSymbolAddress((void**)&Qh, g_Qh);   cudaGetSymbolAddress((void**)&Ql, g_Ql);
    cudaGetSymbolAddress((void**)&Kh, g_Kh);   cudaGetSymbolAddress((void**)&Kl, g_Kl);
    cudaGetSymbolAddress((void**)&Vh, g_Vh);   cudaGetSymbolAddress((void**)&Vl, g_Vl);
    cudaGetSymbolAddress((void**)&Vth, g_Vth); cudaGetSymbolAddress((void**)&Vtl, g_Vtl);
    cudaGetSymbolAddress((void**)&Bh, g_Bh);   cudaGetSymbolAddress((void**)&Bl, g_Bl);
    cudaGetSymbolAddress((void**)&attn_scratch, g_attn);

    const long OUT_E = 4194304L, ATTN_E = 134217728L;
    float* attn = ((long)out_size >= OUT_E + ATTN_E) ? (out + OUT_E) : attn_scratch;

    const int SM_GEMM  = 81920;
    const int SM_FUSED = 143360;
    cudaFuncSetAttribute(hgemm,      cudaFuncAttributeMaxDynamicSharedMemorySize, SM_GEMM);
    cudaFuncSetAttribute(fused_attn, cudaFuncAttributeMaxDynamicSharedMemorySize, SM_FUSED);

    cvt_split<<<4096, 256>>>(query,        qh, ql, 1048576);
    cvt_split<<<4096, 256>>>(input_embeds, xh, xl, 1048576);
    cvt_split<<<1024, 256>>>(wq_w, wqh, wql, 262144);
    cvt_split<<<1024, 256>>>(wk_w, wkh, wkl, 262144);
    cvt_split<<<1024, 256>>>(wv_w, wvh, wvl, 262144);
    cvt_split<<<1024, 256>>>(wo_w, woh, wol, 262144);

    dim3 gP(8, 32);
    hgemm<<<gP, 256, SM_GEMM>>>(qh, ql, wqh, wql, wq_b, nullptr, Qh, Ql, 1024, 1024, 1024, 1024);
    hgemm<<<gP, 256, SM_GEMM>>>(xh, xl, wkh, wkl, wk_b, nullptr, Kh, Kl, 1024, 1024, 1024, 1024);
    hgemm<<<gP, 256, SM_GEMM>>>(xh, xl, wvh, wvl, wv_b, nullptr, Vh, Vl, 1024, 1024, 1024, 1024);

    vtrans<<<dim3(32, 32), 256>>>(Vh, Vl, Vth, Vtl);

    fused_attn<<<dim3(16, 32), 256, SM_FUSED>>>(Qh, Ql, Kh, Kl, Vth, Vtl, mask,
                                                attn, Bh, Bl);

    hgemm<<<gP, 256, SM_GEMM>>>(Bh, Bl, woh, wol, wo_b, out, nullptr, nullptr, 1024, 1024, 1024, 1024);
}

// round 7
// speedup vs baseline: 2.4744x; 1.0801x over previous
#include <cuda_runtime.h>
#include <cuda_bf16.h>
#include <cstdint>

typedef __nv_bfloat16 bf16;

// ---------------------------------------------------------------------------
static __device__ __forceinline__ uint32_t smem_u32(const void* p) {
    uint32_t a;
    asm("{ .reg .u64 t; cvta.to.shared.u64 t, %1; cvt.u32.u64 %0, t; }" : "=r"(a) : "l"(p));
    return a;
}
static __device__ __forceinline__ void mma16816(float* c, const uint32_t* a, const uint32_t* b) {
    asm volatile("mma.sync.aligned.m16n8k16.row.col.f32.bf16.bf16.f32 "
        "{%0,%1,%2,%3}, {%4,%5,%6,%7}, {%8,%9}, {%0,%1,%2,%3};"
        : "+f"(c[0]), "+f"(c[1]), "+f"(c[2]), "+f"(c[3])
        : "r"(a[0]), "r"(a[1]), "r"(a[2]), "r"(a[3]), "r"(b[0]), "r"(b[1]));
}
static __device__ __forceinline__ void mma3(float* c, const uint32_t* ah, const uint32_t* al,
                                            const uint32_t* bh, const uint32_t* bl) {
    mma16816(c, ah, bh); mma16816(c, ah, bl); mma16816(c, al, bh);
}
static __device__ __forceinline__ void ldsm4(uint32_t* r, uint32_t a) {
    asm volatile("ldmatrix.sync.aligned.m8n8.x4.shared.b16 {%0,%1,%2,%3}, [%4];"
        : "=r"(r[0]), "=r"(r[1]), "=r"(r[2]), "=r"(r[3]) : "r"(a));
}
static __device__ __forceinline__ void ldsmA(uint32_t* r, uint32_t base, int m0, int k0, int sbytes, int lane) {
    ldsm4(r, base + (uint32_t)((m0 + (lane & 7) + ((lane >> 3) & 1) * 8) * sbytes
                               + (k0 + ((lane >> 4) << 3)) * 2));
}
static __device__ __forceinline__ void ldsmB(uint32_t* r, uint32_t base, int n0, int k0, int sbytes, int lane) {
    ldsm4(r, base + (uint32_t)((n0 + (lane & 7) + ((lane >> 4) << 3)) * sbytes
                               + (k0 + (((lane >> 3) & 1) << 3)) * 2));
}
#define CP16(sm_, gp_) asm volatile("cp.async.cg.shared.global [%0], [%1], 16;" :: "r"(sm_), "l"(gp_))
#define CPCOMMIT()     asm volatile("cp.async.commit_group;")
#define CPWAIT(n)      asm volatile("cp.async.wait_group %0;" :: "n"(n))

static __device__ __forceinline__ void store_split2(bf16* Ch, bf16* Cl, long off, float x, float y) {
    __align__(4) bf16 h[2] = {__float2bfloat16(x), __float2bfloat16(y)};
    __align__(4) bf16 l[2] = {__float2bfloat16(x - __bfloat162float(h[0])),
                              __float2bfloat16(y - __bfloat162float(h[1]))};
    *(uint32_t*)(Ch + off) = *(uint32_t*)h;
    *(uint32_t*)(Cl + off) = *(uint32_t*)l;
}
static __device__ __forceinline__ void smem_split2(char* ph, char* pl, float x, float y) {
    __align__(4) bf16 h[2] = {__float2bfloat16(x), __float2bfloat16(y)};
    __align__(4) bf16 l[2] = {__float2bfloat16(x - __bfloat162float(h[0])),
                              __float2bfloat16(y - __bfloat162float(h[1]))};
    *(uint32_t*)ph = *(uint32_t*)h;
    *(uint32_t*)pl = *(uint32_t*)l;
}

// ---------------- scratch ----------------
__device__ bf16 g_qh[4194304], g_ql[4194304];
__device__ bf16 g_xh[4194304], g_xl[4194304];
__device__ bf16 g_wqh[1048576], g_wql[1048576];
__device__ bf16 g_wkh[1048576], g_wkl[1048576];
__device__ bf16 g_wvh[1048576], g_wvl[1048576];
__device__ bf16 g_woh[1048576], g_wol[1048576];
__device__ bf16 g_Qh[4194304], g_Ql[4194304];
__device__ bf16 g_Kh[4194304], g_Kl[4194304];
__device__ bf16 g_Vh[4194304], g_Vl[4194304];
__device__ bf16 g_Vth[4194304], g_Vtl[4194304];  // [bh][64 d][2048 tok]
__device__ bf16 g_Bh[4194304], g_Bl[4194304];
__device__ float g_attn[134217728];

// ---------------- merged fp32 -> bf16 hi/lo for all 6 tensors ----------------
// flat float4 index over: q(1048576) x(1048576) wq wk wv wo (262144 each)
__global__ __launch_bounds__(256) void cvt_all(
    const float* __restrict__ s0, const float* __restrict__ s1,
    const float* __restrict__ s2, const float* __restrict__ s3,
    const float* __restrict__ s4, const float* __restrict__ s5,
    bf16* __restrict__ h0, bf16* __restrict__ l0, bf16* __restrict__ h1, bf16* __restrict__ l1,
    bf16* __restrict__ h2, bf16* __restrict__ l2, bf16* __restrict__ h3, bf16* __restrict__ l3,
    bf16* __restrict__ h4, bf16* __restrict__ l4, bf16* __restrict__ h5, bf16* __restrict__ l5)
{
    long i = (long)blockIdx.x * 256 + threadIdx.x;   // < 3145728
    const float* src; bf16 *h, *l; long li;
    if (i < 1048576)      { src = s0; h = h0; l = l0; li = i; }
    else if (i < 2097152) { src = s1; h = h1; l = l1; li = i - 1048576; }
    else {
        long j = i - 2097152;
        int w = (int)(j >> 18);          // 0..3
        li = j & 262143;
        src = (w == 0) ? s2 : (w == 1) ? s3 : (w == 2) ? s4 : s5;
        h   = (w == 0) ? h2 : (w == 1) ? h3 : (w == 2) ? h4 : h5;
        l   = (w == 0) ? l2 : (w == 1) ? l3 : (w == 2) ? l4 : l5;
    }
    float4 v = ((const float4*)src)[li];
    float f[4] = {v.x, v.y, v.z, v.w};
    __align__(8) bf16 hv[4], lv[4];
#pragma unroll
    for (int j = 0; j < 4; j++) {
        hv[j] = __float2bfloat16(f[j]);
        lv[j] = __float2bfloat16(f[j] - __bfloat162float(hv[j]));
    }
    ((uint2*)h)[li] = *(uint2*)hv;
    ((uint2*)l)[li] = *(uint2*)lv;
}

// ---------------------------------------------------------------------------
// hgemm: C = A·B^T + bias (bf16 hi/lo, 3-product), 128x128, cp.async pipelined
// ---------------------------------------------------------------------------
__global__ __launch_bounds__(256) void hgemm(
    const bf16* __restrict__ Ah, const bf16* __restrict__ Al,
    const bf16* __restrict__ Bh, const bf16* __restrict__ Bl,
    const float* __restrict__ bias, float* __restrict__ Cf,
    bf16* __restrict__ Ch, bf16* __restrict__ Cl,
    int K, int lda, int ldb, int ldc)
{
    extern __shared__ char sm[];
    uint32_t sb = smem_u32(sm);
    int t = threadIdx.x, lane = t & 31, wid = t >> 5;
    int wm = wid & 3, wn = wid >> 2;
    long m0 = blockIdx.y * 128, n0 = blockIdx.x * 128;

    const bf16* g0 = Ah + m0 * lda;
    const bf16* g1 = Al + m0 * lda;
    const bf16* g2 = Bh + n0 * ldb;
    const bf16* g3 = Bl + n0 * ldb;

#define G_ISSUE(c_, buf_) do {                                                  \
    int _c = (c_); uint32_t _bs = sb + (buf_) * 40960;                          \
    _Pragma("unroll")                                                           \
    for (int i = 0; i < 8; i++) {                                               \
        const int tile = i >> 1;                                                \
        int w = t + 256 * (i & 1);                                              \
        int row = w >> 2, sg = w & 3;                                           \
        const bf16* gp = (tile == 0 ? g0 : tile == 1 ? g1 : tile == 2 ? g2 : g3)\
            + (long)row * (tile < 2 ? lda : ldb) + _c * 32 + sg * 8;            \
        CP16(_bs + tile * 10240 + row * 80 + sg * 16, gp);                      \
    }                                                                           \
    CPCOMMIT();                                                                 \
} while (0)

    float acc[2][8][4] = {};
    int nc = K >> 5;
    G_ISSUE(0, 0);
    G_ISSUE(1, 1);
    for (int c = 0; c < nc; c++) {
        if (c + 1 < nc) { CPWAIT(1); } else { CPWAIT(0); }
        __syncthreads();
        uint32_t bAh = sb + (c & 1) * 40960, bAl = bAh + 10240;
        uint32_t bBh = bAh + 20480, bBl = bAh + 30720;
#pragma unroll
        for (int k0 = 0; k0 < 32; k0 += 16) {
            uint32_t ah[2][4], al[2][4], bhf[4][4], blf[4][4];
#pragma unroll
            for (int mt = 0; mt < 2; mt++) {
                ldsmA(ah[mt], bAh, wm * 32 + mt * 16, k0, 80, lane);
                ldsmA(al[mt], bAl, wm * 32 + mt * 16, k0, 80, lane);
            }
#pragma unroll
            for (int p = 0; p < 4; p++) {
                ldsmB(bhf[p], bBh, wn * 64 + p * 16, k0, 80, lane);
                ldsmB(blf[p], bBl, wn * 64 + p * 16, k0, 80, lane);
            }
#pragma unroll
            for (int mt = 0; mt < 2; mt++)
#pragma unroll
                for (int p = 0; p < 4; p++) {
                    mma3(acc[mt][p * 2],     ah[mt], al[mt], &bhf[p][0], &blf[p][0]);
                    mma3(acc[mt][p * 2 + 1], ah[mt], al[mt], &bhf[p][2], &blf[p][2]);
                }
        }
        __syncthreads();
        if (c + 2 < nc) G_ISSUE(c + 2, c & 1);
    }
#undef G_ISSUE

#pragma unroll
    for (int mt = 0; mt < 2; mt++)
#pragma unroll
        for (int nt = 0; nt < 8; nt++) {
            float* cc = acc[mt][nt];
            long r0 = m0 + wm * 32 + mt * 16 + (lane >> 2);
            int col = (int)n0 + wn * 64 + nt * 8 + 2 * (lane & 3);
            float b0 = bias[col], b1 = bias[col + 1];
            float f0 = cc[0] + b0, f1 = cc[1] + b1, f2 = cc[2] + b0, f3 = cc[3] + b1;
            if (Cf) {
                *(float2*)(Cf + r0 * ldc + col) = make_float2(f0, f1);
                *(float2*)(Cf + (r0 + 8) * ldc + col) = make_float2(f2, f3);
            }
            if (Ch) {
                store_split2(Ch, Cl, r0 * ldc + col, f0, f1);
                store_split2(Ch, Cl, (r0 + 8) * ldc + col, f2, f3);
            }
        }
}

// ---------------------------------------------------------------------------
// vtrans: V split [4096 tok,1024] -> per (b,h): [64 d][2048 tok]
// ---------------------------------------------------------------------------
__global__ __launch_bounds__(256) void vtrans(
    const bf16* __restrict__ Vh, const bf16* __restrict__ Vl,
    bf16* __restrict__ Th, bf16* __restrict__ Tl) {
    __shared__ bf16 sh[64][72], sl[64][72];
    int t = threadIdx.x, tt = blockIdx.x, bh = blockIdx.y;
    int b = bh >> 4, h = bh & 15;
    const bf16* srch = Vh + ((long)b * 2048 + tt * 64) * 1024 + h * 64;
    const bf16* srcl = Vl + ((long)b * 2048 + tt * 64) * 1024 + h * 64;
#pragma unroll
    for (int i = 0; i < 2; i++) {
        int s = t + 256 * i, row = s >> 3, seg = s & 7;
        *(uint4*)&sh[row][seg * 8] = *(const uint4*)(srch + (long)row * 1024 + seg * 8);
        *(uint4*)&sl[row][seg * 8] = *(const uint4*)(srcl + (long)row * 1024 + seg * 8);
    }
    __syncthreads();
    bf16* dh = Th + (long)bh * 64 * 2048 + tt * 64;
    bf16* dl = Tl + (long)bh * 64 * 2048 + tt * 64;
#pragma unroll
    for (int i = 0; i < 2; i++) {
        int s = t + 256 * i, d = s >> 3, seg = s & 7;
        __align__(16) bf16 th[8], tl[8];
#pragma unroll
        for (int j = 0; j < 8; j++) { th[j] = sh[seg * 8 + j][d]; tl[j] = sl[seg * 8 + j][d]; }
        *(uint4*)(dh + (long)d * 2048 + seg * 8) = *(uint4*)th;
        *(uint4*)(dl + (long)d * 2048 + seg * 8) = *(uint4*)tl;
    }
}

// ---------------------------------------------------------------------------
// fused_attn (cp.async pipelined):
//   pass A: rowsum of exp(QK^T + maskadd)
//   pass B: recompute scores, write attn = e*inv, P->smem, O += P·V
// smem (bytes):
//   Q hi @0, Q lo @18432                 (stride 144)
//   K buf0 @36864, buf1 @73728           (hi +0, lo +18432; stride 144)
//   P hi @110592, P lo @145408           (stride 272)
//   V hi @180224, V lo @197632           (stride 272)
//   msk @215040 (2048 f), part @223232 (256 f), invs @224256 (128 f)
// total 224768
// ---------------------------------------------------------------------------
#define SQ_H  0
#define SQ_L  18432
#define SKBUF(b) (36864 + (b) * 36864)
#define SP_H  110592
#define SP_L  145408
#define SV_H  180224
#define SV_L  197632
#define SMSK  215040
#define SPART 223232
#define SINVS 224256
#define SM_FUSED 224768

__global__ __launch_bounds__(256, 1) void fused_attn(
    const bf16* __restrict__ Qh, const bf16* __restrict__ Ql,
    const bf16* __restrict__ Kh, const bf16* __restrict__ Kl,
    const bf16* __restrict__ Vth, const bf16* __restrict__ Vtl,
    const float* __restrict__ mask,
    float* __restrict__ A, bf16* __restrict__ Bh, bf16* __restrict__ Bl)
{
    extern __shared__ char sm[];
    uint32_t sb = smem_u32(sm);
    int t = threadIdx.x, lane = t & 31, wid = t >> 5;
    int wm = wid & 3, wn = wid >> 2;
    int qt = blockIdx.x, bh = blockIdx.y;
    int b = bh >> 4, h = bh & 15;

    const bf16* qh = Qh + ((long)b * 2048 + qt * 128) * 1024 + h * 64;
    const bf16* ql = Ql + ((long)b * 2048 + qt * 128) * 1024 + h * 64;
    const bf16* kh = Kh + (long)b * 2048 * 1024 + h * 64;
    const bf16* kl = Kl + (long)b * 2048 * 1024 + h * 64;
    const bf16* vth = Vth + (long)bh * 64 * 2048;
    const bf16* vtl = Vtl + (long)bh * 64 * 2048;
    float* Abh = A + ((long)bh * 2048 + qt * 128) * 2048;
    const float* mrow = mask + (long)b * 2048;

    float* msk  = (float*)(sm + SMSK);
    float* part = (float*)(sm + SPART);
    float* invs = (float*)(sm + SINVS);

// issue cp.async for K tile kt into buffer buf (hi+lo)
#define KISSUE(kt_, buf_) do {                                                   \
    int _kt = (kt_); uint32_t _kb = sb + SKBUF(buf_);                            \
    _Pragma("unroll")                                                            \
    for (int i = 0; i < 8; i++) {                                                \
        const int tile = i >> 2;                                                 \
        int w = t + 256 * (i & 3);                                               \
        int row = w >> 3, sg = w & 7;                                            \
        const bf16* src = (tile ? kl : kh) + (long)(_kt * 128 + row) * 1024 + sg * 8; \
        CP16(_kb + tile * 18432 + row * 144 + sg * 16, src);                     \
    }                                                                            \
    CPCOMMIT();                                                                  \
} while (0)

#define VISSUE(kt_) do {                                                         \
    int _kt = (kt_);                                                             \
    _Pragma("unroll")                                                            \
    for (int i = 0; i < 8; i++) {                                                \
        const int tile = i >> 2;                                                 \
        int w = t + 256 * (i & 3);                                               \
        int row = w >> 4, sg = w & 15;                                           \
        const bf16* src = (tile ? vtl : vth) + (long)row * 2048 + _kt * 128 + sg * 8; \
        CP16(sb + (tile ? SV_L : SV_H) + row * 272 + sg * 16, src);              \
    }                                                                            \
    CPCOMMIT();                                                                  \
} while (0)

    // prologue: Q tiles (plain), full mask row, K(0) via cp.async
    KISSUE(0, 0);
#pragma unroll
    for (int i = 0; i < 8; i++) {
        const int tile = i >> 2;
        int w = t + 256 * (i & 3);
        int row = w >> 3, sg = w & 7;
        const bf16* src = (tile ? ql : qh) + (long)row * 1024 + sg * 8;
        *(uint4*)(sm + (tile ? SQ_L : SQ_H) + row * 144 + sg * 16) = *(const uint4*)src;
    }
#pragma unroll
    for (int j = 0; j < 8; j++) {
        int idx = t + 256 * j;
        msk[idx] = (1.0f - mrow[idx]) * (-1e9f);
    }

    // ---------------- pass A: rowsum only ----------------
    float rs[4] = {0.f, 0.f, 0.f, 0.f};
    for (int kt = 0; kt < 16; kt++) {
        CPWAIT(0);
        __syncthreads();                   // K(kt) ready; prior buffer reads done
        if (kt + 1 < 16) KISSUE(kt + 1, (kt + 1) & 1);

        uint32_t kb = sb + SKBUF(kt & 1);
        float acc[2][8][4] = {};
#pragma unroll
        for (int k0 = 0; k0 < 64; k0 += 16) {
            uint32_t ah[2][4], al[2][4], bhf[4][4], blf[4][4];
#pragma unroll
            for (int mt = 0; mt < 2; mt++) {
                ldsmA(ah[mt], sb + SQ_H, wm * 32 + mt * 16, k0, 144, lane);
                ldsmA(al[mt], sb + SQ_L, wm * 32 + mt * 16, k0, 144, lane);
            }
#pragma unroll
            for (int p = 0; p < 4; p++) {
                ldsmB(bhf[p], kb,         wn * 64 + p * 16, k0, 144, lane);
                ldsmB(blf[p], kb + 18432, wn * 64 + p * 16, k0, 144, lane);
            }
#pragma unroll
            for (int mt = 0; mt < 2; mt++)
#pragma unroll
                for (int p = 0; p < 4; p++) {
                    mma3(acc[mt][p * 2],     ah[mt], al[mt], &bhf[p][0], &blf[p][0]);
                    mma3(acc[mt][p * 2 + 1], ah[mt], al[mt], &bhf[p][2], &blf[p][2]);
                }
        }
#pragma unroll
        for (int mt = 0; mt < 2; mt++)
#pragma unroll
            for (int nt = 0; nt < 8; nt++) {
                float* cc = acc[mt][nt];
                int cl = kt * 128 + wn * 64 + nt * 8 + 2 * (lane & 3);
                float m0v = msk[cl], m1v = msk[cl + 1];
                rs[mt * 2 + 0] += __expf(cc[0] + m0v) + __expf(cc[1] + m1v);
                rs[mt * 2 + 1] += __expf(cc[2] + m0v) + __expf(cc[3] + m1v);
            }
    }

    // K(0) for pass B (buf0; its last reads were pass A kt=14, long done)
    KISSUE(0, 0);

    // reduce rowsum -> invs[128]
#pragma unroll
    for (int i = 0; i < 4; i++) {
        rs[i] += __shfl_xor_sync(0xffffffffu, rs[i], 1);
        rs[i] += __shfl_xor_sync(0xffffffffu, rs[i], 2);
    }
    __syncthreads();                       // pass A reads fully done before part writes? (part fresh region; sync for store/load order below)
    if ((lane & 3) == 0) {
#pragma unroll
        for (int mt = 0; mt < 2; mt++)
#pragma unroll
            for (int hf = 0; hf < 2; hf++)
                part[wn * 128 + wm * 32 + mt * 16 + hf * 8 + (lane >> 2)] = rs[mt * 2 + hf];
    }
    __syncthreads();
    if (t < 128) invs[t] = 1.0f / (part[t] + part[128 + t]);
    __syncthreads();

    float invr[2][2];
#pragma unroll
    for (int mt = 0; mt < 2; mt++) {
        invr[mt][0] = invs[wm * 32 + mt * 16 + (lane >> 2)];
        invr[mt][1] = invs[wm * 32 + mt * 16 + 8 + (lane >> 2)];
    }

    // ---------------- pass B ----------------
    float oacc[2][4][4] = {};
    for (int kt = 0; kt < 16; kt++) {
        CPWAIT(0);
        __syncthreads();                   // K(kt) ready; V/P/K prior reads done
        VISSUE(kt);                        // V first (released by wait_group 1)
        if (kt + 1 < 16) KISSUE(kt + 1, (kt + 1) & 1);

        uint32_t kb = sb + SKBUF(kt & 1);
        float acc[2][8][4] = {};
#pragma unroll
        for (int k0 = 0; k0 < 64; k0 += 16) {
            uint32_t ah[2][4], al[2][4], bhf[4][4], blf[4][4];
#pragma unroll
            for (int mt = 0; mt < 2; mt++) {
                ldsmA(ah[mt], sb + SQ_H, wm * 32 + mt * 16, k0, 144, lane);
                ldsmA(al[mt], sb + SQ_L, wm * 32 + mt * 16, k0, 144, lane);
            }
#pragma unroll
            for (int p = 0; p < 4; p++) {
                ldsmB(bhf[p], kb,         wn * 64 + p * 16, k0, 144, lane);
                ldsmB(blf[p], kb + 18432, wn * 64 + p * 16, k0, 144, lane);
            }
#pragma unroll
            for (int mt = 0; mt < 2; mt++)
#pragma unroll
                for (int p = 0; p < 4; p++) {
                    mma3(acc[mt][p * 2],     ah[mt], al[mt], &bhf[p][0], &blf[p][0]);
                    mma3(acc[mt][p * 2 + 1], ah[mt], al[mt], &bhf[p][2], &blf[p][2]);
                }
        }

        // epilogue: normalize, write attn, split P -> smem
#pragma unroll
        for (int mt = 0; mt < 2; mt++)
#pragma unroll
            for (int nt = 0; nt < 8; nt++) {
                float* cc = acc[mt][nt];
                int r0 = wm * 32 + mt * 16 + (lane >> 2);
                int cl = wn * 64 + nt * 8 + 2 * (lane & 3);
                float m0v = msk[kt * 128 + cl], m1v = msk[kt * 128 + cl + 1];
                float e0 = __expf(cc[0] + m0v) * invr[mt][0];
                float e1 = __expf(cc[1] + m1v) * invr[mt][0];
                float e2 = __expf(cc[2] + m0v) * invr[mt][1];
                float e3 = __expf(cc[3] + m1v) * invr[mt][1];
                *(float2*)(Abh + (long)r0 * 2048 + kt * 128 + cl)       = make_float2(e0, e1);
                *(float2*)(Abh + (long)(r0 + 8) * 2048 + kt * 128 + cl) = make_float2(e2, e3);
                smem_split2(sm + SP_H + r0 * 272 + cl * 2,
                            sm + SP_L + r0 * 272 + cl * 2, e0, e1);
                smem_split2(sm + SP_H + (r0 + 8) * 272 + cl * 2,
                            sm + SP_L + (r0 + 8) * 272 + cl * 2, e2, e3);
            }

        if (kt + 1 < 16) { CPWAIT(1); } else { CPWAIT(0); }
        __syncthreads();                   // V(kt) + P visible

        // O += P · V^T
#pragma unroll
        for (int k0 = 0; k0 < 128; k0 += 16) {
            uint32_t ah[2][4], al[2][4], bhf[2][4], blf[2][4];
#pragma unroll
            for (int mt = 0; mt < 2; mt++) {
                ldsmA(ah[mt], sb + SP_H, wm * 32 + mt * 16, k0, 272, lane);
                ldsmA(al[mt], sb + SP_L, wm * 32 + mt * 16, k0, 272, lane);
            }
#pragma unroll
            for (int p = 0; p < 2; p++) {
                ldsmB(bhf[p], sb + SV_H, wn * 32 + p * 16, k0, 272, lane);
                ldsmB(blf[p], sb + SV_L, wn * 32 + p * 16, k0, 272, lane);
            }
#pragma unroll
            for (int mt = 0; mt < 2; mt++)
#pragma unroll
                for (int p = 0; p < 2; p++) {
                    mma3(oacc[mt][p * 2],     ah[mt], al[mt], &bhf[p][0], &blf[p][0]);
                    mma3(oacc[mt][p * 2 + 1], ah[mt], al[mt], &bhf[p][2], &blf[p][2]);
                }
        }
    }

    // write blended split [b, q, h*64+d]
#pragma unroll
    for (int mt = 0; mt < 2; mt++)
#pragma unroll
        for (int nt = 0; nt < 4; nt++) {
            float* cc = oacc[mt][nt];
            long r0 = (long)b * 2048 + qt * 128 + wm * 32 + mt * 16 + (lane >> 2);
            int col = h * 64 + wn * 32 + nt * 8 + 2 * (lane & 3);
            store_split2(Bh, Bl, r0 * 1024 + col, cc[0], cc[1]);
            store_split2(Bh, Bl, (r0 + 8) * 1024 + col, cc[2], cc[3]);
        }
}

// ===========================================================================
extern "C" void kernel_launch(void* const* d_in, const int* in_sizes, int n_in,
                              void* d_out, int out_size) {
    (void)in_sizes; (void)n_in;
    const float* query        = (const float*)d_in[0];
    const float* input_embeds = (const float*)d_in[1];
    const float* mask         = (const float*)d_in[2];
    const float* wq_w = (const float*)d_in[3];
    const float* wq_b = (const float*)d_in[4];
    const float* wk_w = (const float*)d_in[5];
    const float* wk_b = (const float*)d_in[6];
    const float* wv_w = (const float*)d_in[7];
    const float* wv_b = (const float*)d_in[8];
    const float* wo_w = (const float*)d_in[9];
    const float* wo_b = (const float*)d_in[10];
    float* out = (float*)d_out;

    bf16 *qh, *ql, *xh, *xl, *wqh, *wql, *wkh, *wkl, *wvh, *wvl, *woh, *wol;
    bf16 *Qh, *Ql, *Kh, *Kl, *Vh, *Vl, *Vth, *Vtl, *Bh, *Bl;
    float *attn_scratch;
    cudaGetSymbolAddress((void**)&qh, g_qh);   cudaGetSymbolAddress((void**)&ql, g_ql);
    cudaGetSymbolAddress((void**)&xh, g_xh);   cudaGetSymbolAddress((void**)&xl, g_xl);
    cudaGetSymbolAddress((void**)&wqh, g_wqh); cudaGetSymbolAddress((void**)&wql, g_wql);
    cudaGetSymbolAddress((void**)&wkh, g_wkh); cudaGetSymbolAddress((void**)&wkl, g_wkl);
    cudaGetSymbolAddress((void**)&wvh, g_wvh); cudaGetSymbolAddress((void**)&wvl, g_wvl);
    cudaGetSymbolAddress((void**)&woh, g_woh); cudaGetSymbolAddress((void**)&wol, g_wol);
    cudaGetSymbolAddress((void**)&Qh, g_Qh);   cudaGetSymbolAddress((void**)&Ql, g_Ql);
    cudaGetSymbolAddress((void**)&Kh, g_Kh);   cudaGetSymbolAddress((void**)&Kl, g_Kl);
    cudaGetSymbolAddress((void**)&Vh, g_Vh);   cudaGetSymbolAddress((void**)&Vl, g_Vl);
    cudaGetSymbolAddress((void**)&Vth, g_Vth); cudaGetSymbolAddress((void**)&Vtl, g_Vtl);
    cudaGetSymbolAddress((void**)&Bh, g_Bh);   cudaGetSymbolAddress((void**)&Bl, g_Bl);
    cudaGetSymbolAddress((void**)&attn_scratch, g_attn);

    const long OUT_E = 4194304L, ATTN_E = 134217728L;
    float* attn = ((long)out_size >= OUT_E + ATTN_E) ? (out + OUT_E) : attn_scratch;

    const int SM_GEMM = 81920;
    cudaFuncSetAttribute(hgemm,      cudaFuncAttributeMaxDynamicSharedMemorySize, SM_GEMM);
    cudaFuncSetAttribute(fused_attn, cudaFuncAttributeMaxDynamicSharedMemorySize, SM_FUSED);

    // [0] merged converts
    cvt_all<<<12288, 256>>>(query, input_embeds, wq_w, wk_w, wv_w, wo_w,
                            qh, ql, xh, xl, wqh, wql, wkh, wkl, wvh, wvl, woh, wol);

    // [1..3] projections
    dim3 gP(8, 32);
    hgemm<<<gP, 256, SM_GEMM>>>(qh, ql, wqh, wql, wq_b, nullptr, Qh, Ql, 1024, 1024, 1024, 1024);
    hgemm<<<gP, 256, SM_GEMM>>>(xh, xl, wkh, wkl, wk_b, nullptr, Kh, Kl, 1024, 1024, 1024, 1024);
    hgemm<<<gP, 256, SM_GEMM>>>(xh, xl, wvh, wvl, wv_b, nullptr, Vh, Vl, 1024, 1024, 1024, 1024);

    // [4] V transpose
    vtrans<<<dim3(32, 32), 256>>>(Vh, Vl, Vth, Vtl);

    // [5] fused attention  (ncu -s 5 -c 1 lands here)
    fused_attn<<<dim3(16, 32), 256, SM_FUSED>>>(Qh, Ql, Kh, Kl, Vth, Vtl, mask,
                                                attn, Bh, Bl);

    // [6] out projection
    hgemm<<<gP, 256, SM_GEMM>>>(Bh, Bl, woh, wol, wo_b, out, nullptr, nullptr, 1024, 1024, 1024, 1024);
}